// round 1
// baseline (speedup 1.0000x reference)
#include <cuda_runtime.h>
#include <math.h>

#define N_NODES 5120
#define TBL 256
#define LATENT 128
#define N_GRAPHS 64
#define N_EDGES 163840
#define NN 80
#define N2 6400
#define HID 12800

typedef unsigned long long ull;

// ---------------- scratch (static device allocations; no cudaMalloc) --------
__device__ float g_deg[N_NODES];
__device__ float g_dinv[N_NODES];
__device__ float g_hs[N_NODES * LATENT];     // dinv-prescaled h = (x@Wg)*dinv[row]
__device__ float g_agg[N_NODES * LATENT];    // scatter accumulator
__device__ float g_Z[N_GRAPHS * N2];         // flattened outer products [64, 6400]
__device__ float g_H1[N_GRAPHS * HID];       // hidden activations [64, 12800]

// ---------------- packed f32x2 helpers (Blackwell FFMA2 path) ---------------
__device__ __forceinline__ ull pack2(float x, float y) {
    ull r;
    asm("mov.b64 %0, {%1, %2};" : "=l"(r) : "f"(x), "f"(y));
    return r;
}
__device__ __forceinline__ void unpack2(ull v, float& x, float& y) {
    asm("mov.b64 {%0, %1}, %2;" : "=f"(x), "=f"(y) : "l"(v));
}
__device__ __forceinline__ void fma2(ull& d, ull a, ull b) {
    // d = a * b + d   (elementwise on packed f32 pairs)
    asm("fma.rn.f32x2 %0, %1, %2, %0;" : "+l"(d) : "l"(a), "l"(b));
}

// ---------------- K0: zero deg + agg ----------------------------------------
__global__ void k_zero() {
    int t = blockIdx.x * blockDim.x + threadIdx.x;   // grid sized exactly
    if (t < N_NODES) g_deg[t] = 0.0f;
    else g_agg[t - N_NODES] = 0.0f;
}

// ---------------- K1: degree counts -----------------------------------------
__global__ void k_deg(const int* __restrict__ ei) {
    int e = blockIdx.x * 256 + threadIdx.x;
    if (e < N_EDGES) atomicAdd(&g_deg[ei[N_EDGES + e]], 1.0f);
}

// ---------------- K2: dinv ---------------------------------------------------
__global__ void k_dinv() {
    int i = blockIdx.x * 256 + threadIdx.x;
    if (i < N_NODES) {
        float d = g_deg[i];
        g_dinv[i] = (d > 0.0f) ? rsqrtf(d) : 0.0f;
    }
}

// ---------------- K3: hs = (x @ Wg) * dinv[row] ------------------------------
// block: 16 rows x 128 cols, 256 threads; thread = (col, row-half of 8 rows)
__global__ void k_gemm_h(const float* __restrict__ x, const float* __restrict__ Wg) {
    __shared__ float xs[16][TBL];
    int tid = threadIdx.x;
    int col = tid & 127;
    int rh = tid >> 7;              // 0..1
    int rowblk = blockIdx.x * 16;

#pragma unroll
    for (int it = 0; it < 16; it++) {
        int idx = tid + it * 256;
        int r = idx >> 8, k = idx & 255;
        xs[r][k] = x[(size_t)(rowblk + r) * TBL + k];
    }
    __syncthreads();

    float acc[8];
#pragma unroll
    for (int r = 0; r < 8; r++) acc[r] = 0.0f;

#pragma unroll 8
    for (int k = 0; k < TBL; k++) {
        float w = Wg[k * LATENT + col];
#pragma unroll
        for (int r = 0; r < 8; r++) acc[r] += xs[rh * 8 + r][k] * w;
    }

#pragma unroll
    for (int r = 0; r < 8; r++) {
        int node = rowblk + rh * 8 + r;
        g_hs[node * LATENT + col] = acc[r] * g_dinv[node];
    }
}

// ---------------- K4: scatter agg[dst] += hs[src] ----------------------------
// 32 threads per edge, each handles 4 consecutive features
__global__ void k_scatter(const int* __restrict__ ei) {
    int t = blockIdx.x * 256 + threadIdx.x;
    int e = t >> 5;
    int lane = t & 31;
    if (e < N_EDGES) {
        int s = ei[e];
        int d = ei[N_EDGES + e];
        const float4 v = *(const float4*)&g_hs[s * LATENT + lane * 4];
        float* p = &g_agg[d * LATENT + lane * 4];
        atomicAdd(p + 0, v.x);
        atomicAdd(p + 1, v.y);
        atomicAdd(p + 2, v.z);
        atomicAdd(p + 3, v.w);
    }
}

// ---------------- K5: z = relu(dinv*agg + bg); G[b] = z z^T ------------------
// one block per graph; 256 threads each compute a 5x5 tile of the 80x80 gram
__global__ void k_outer(const float* __restrict__ bg) {
    __shared__ float zs[NN][129];   // pad 129: 5m mod 32 distinct -> conflict-free
    int b = blockIdx.x;
    int tid = threadIdx.x;

    for (int idx = tid; idx < NN * LATENT; idx += 256) {
        int n = idx >> 7, c = idx & 127;
        int node = b * NN + n;
        float v = g_dinv[node] * g_agg[node * LATENT + c] + bg[c];
        zs[n][c] = (v > 0.0f) ? v : 0.0f;
    }
    __syncthreads();

    int tn = tid >> 4, tm = tid & 15;
    int n0 = tn * 5, m0 = tm * 5;
    float acc[5][5];
#pragma unroll
    for (int i = 0; i < 5; i++)
#pragma unroll
        for (int j = 0; j < 5; j++) acc[i][j] = 0.0f;

#pragma unroll 4
    for (int c = 0; c < LATENT; c++) {
        float zn[5], zm[5];
#pragma unroll
        for (int i = 0; i < 5; i++) { zn[i] = zs[n0 + i][c]; zm[i] = zs[m0 + i][c]; }
#pragma unroll
        for (int i = 0; i < 5; i++)
#pragma unroll
            for (int j = 0; j < 5; j++) acc[i][j] += zn[i] * zm[j];
    }

    float* out = &g_Z[b * N2];
#pragma unroll
    for (int i = 0; i < 5; i++)
#pragma unroll
        for (int j = 0; j < 5; j++)
            out[(n0 + i) * NN + (m0 + j)] = acc[i][j];
}

// ---------------- K6/K7: big skinny GEMM, M=64, f32x2 FFMA -------------------
// block tile: 64 rows x 64 cols, 128 threads
// thread tile: 8 rows (4 packed row-pairs) x 4 cols; K staged in chunks of 32
// which==0: A=g_Z,  O=g_H1, act=relu
// which==1: A=g_H1, O=out_ext, act=sigmoid
__global__ void __launch_bounds__(128)
k_gemm64(const float* __restrict__ W, const float* __restrict__ bias,
         float* __restrict__ out_ext, int which, int K, int N, int act) {
    __shared__ float2 As2[32][33];  // As2[k][rp] = (A[2rp][k0+k], A[2rp+1][k0+k])

    const float* __restrict__ A = (which == 0) ? g_Z : g_H1;
    float* __restrict__ O = (which == 0) ? g_H1 : out_ext;

    int tid = threadIdx.x;
    int jg = tid & 15;              // 16 col groups of 4
    int rg = tid >> 4;              // 8 row groups of 8
    int col0 = blockIdx.x * 64 + jg * 4;
    int row0 = rg * 8;

    ull acc[4][4];
#pragma unroll
    for (int i = 0; i < 4; i++)
#pragma unroll
        for (int c = 0; c < 4; c++) acc[i][c] = pack2(0.0f, 0.0f);

    for (int k0 = 0; k0 < K; k0 += 32) {
        __syncthreads();
        // stage A chunk [64 x 32] as packed row-pairs
#pragma unroll
        for (int it = 0; it < 4; it++) {
            int idx4 = tid + it * 128;          // 0..511 float4s
            int r = idx4 >> 3;
            int k4 = (idx4 & 7) * 4;
            float4 v = *(const float4*)(A + (size_t)r * K + k0 + k4);
            int rp = r >> 1;
            if ((r & 1) == 0) {
                As2[k4 + 0][rp].x = v.x; As2[k4 + 1][rp].x = v.y;
                As2[k4 + 2][rp].x = v.z; As2[k4 + 3][rp].x = v.w;
            } else {
                As2[k4 + 0][rp].y = v.x; As2[k4 + 1][rp].y = v.y;
                As2[k4 + 2][rp].y = v.z; As2[k4 + 3][rp].y = v.w;
            }
        }
        __syncthreads();

        const float* Wp = W + (size_t)k0 * N + col0;
#pragma unroll
        for (int k = 0; k < 32; k++) {
            float4 w = *(const float4*)(Wp + (size_t)k * N);
            ull w0 = pack2(w.x, w.x);
            ull w1 = pack2(w.y, w.y);
            ull w2 = pack2(w.z, w.z);
            ull w3 = pack2(w.w, w.w);
#pragma unroll
            for (int i = 0; i < 4; i++) {
                ull a = *(const ull*)&As2[k][rg * 4 + i];
                fma2(acc[i][0], a, w0);
                fma2(acc[i][1], a, w1);
                fma2(acc[i][2], a, w2);
                fma2(acc[i][3], a, w3);
            }
        }
    }

    // epilogue
#pragma unroll
    for (int c = 0; c < 4; c++) {
        float bb = bias[col0 + c];
#pragma unroll
        for (int i = 0; i < 4; i++) {
            float v0, v1;
            unpack2(acc[i][c], v0, v1);
            v0 += bb; v1 += bb;
            if (act == 0) {
                v0 = (v0 > 0.0f) ? v0 : 0.0f;
                v1 = (v1 > 0.0f) ? v1 : 0.0f;
            } else {
                v0 = 1.0f / (1.0f + expf(-v0));
                v1 = 1.0f / (1.0f + expf(-v1));
            }
            O[(size_t)(row0 + 2 * i) * N + col0 + c] = v0;
            O[(size_t)(row0 + 2 * i + 1) * N + col0 + c] = v1;
        }
    }
}

// ---------------- launch -----------------------------------------------------
extern "C" void kernel_launch(void* const* d_in, const int* in_sizes, int n_in,
                              void* d_out, int out_size) {
    const float* x  = (const float*)d_in[0];
    const int*   ei = (const int*)d_in[1];
    const float* Wg = (const float*)d_in[2];
    const float* bg = (const float*)d_in[3];
    const float* W1 = (const float*)d_in[4];
    const float* b1 = (const float*)d_in[5];
    const float* W2 = (const float*)d_in[6];
    const float* b2 = (const float*)d_in[7];
    float* out = (float*)d_out;

    // zero deg (5120) + agg (655360): 660480 threads exactly
    k_zero<<<2580, 256>>>();
    k_deg<<<(N_EDGES + 255) / 256, 256>>>(ei);
    k_dinv<<<(N_NODES + 255) / 256, 256>>>();
    k_gemm_h<<<N_NODES / 16, 256>>>(x, Wg);
    k_scatter<<<(N_EDGES * 32) / 256, 256>>>(ei);
    k_outer<<<N_GRAPHS, 256>>>(bg);
    k_gemm64<<<HID / 64, 128>>>(W1, b1, nullptr, 0, N2, HID, 0);
    k_gemm64<<<N2 / 64, 128>>>(W2, b2, out, 1, HID, N2, 1);
}

// round 4
// speedup vs baseline: 5.8686x; 5.8686x over previous
#include <cuda_runtime.h>
#include <math.h>
#include <stdint.h>

#define N_NODES 5120
#define TBL 256
#define LATENT 128
#define N_GRAPHS 64
#define N_EDGES 163840
#define NN 80
#define N2 6400
#define HID 12800

#define KC 64          // k-chunk per pipeline stage
#define S1 2           // split-K for GEMM1
#define S2 4           // split-K for GEMM2

typedef unsigned long long ull;

// ---------------- scratch (static device arrays; no cudaMalloc) -------------
__device__ float g_deg[N_NODES];
__device__ float g_dinv[N_NODES];
__device__ float g_hs[N_NODES * LATENT];
__device__ float g_agg[N_NODES * LATENT];
__device__ float g_Z[N_GRAPHS * N2];               // [64][6400]
__device__ float g_ZT[N2 * 128];                    // dup-transposed: [6400][128]
__device__ float g_H1T[HID * 128];                  // dup-transposed: [12800][128]
__device__ float g_P1[S1 * N_GRAPHS * HID];         // GEMM1 partials
__device__ float g_P2[S2 * N_GRAPHS * N2];          // GEMM2 partials

// ---------------- helpers ----------------------------------------------------
__device__ __forceinline__ void unpack2(ull v, float& x, float& y) {
    asm("mov.b64 {%0, %1}, %2;" : "=f"(x), "=f"(y) : "l"(v));
}
__device__ __forceinline__ void fma2(ull& d, ull a, ull b) {
    asm("fma.rn.f32x2 %0, %1, %2, %0;" : "+l"(d) : "l"(a), "l"(b));
}
__device__ __forceinline__ void cp_async16(uint32_t dst, const void* src) {
    asm volatile("cp.async.cg.shared.global [%0], [%1], 16;\n" :: "r"(dst), "l"(src));
}
__device__ __forceinline__ void cp_commit() {
    asm volatile("cp.async.commit_group;\n" ::: "memory");
}
template<int N>
__device__ __forceinline__ void cp_wait() {
    asm volatile("cp.async.wait_group %0;\n" :: "n"(N) : "memory");
}

// ---------------- K0: zero deg + agg ----------------------------------------
__global__ void k_zero() {
    int t = blockIdx.x * blockDim.x + threadIdx.x;
    if (t < N_NODES) g_deg[t] = 0.0f;
    else g_agg[t - N_NODES] = 0.0f;
}

// ---------------- K1: degree counts -----------------------------------------
__global__ void k_deg(const int* __restrict__ ei) {
    int e = blockIdx.x * 256 + threadIdx.x;
    if (e < N_EDGES) atomicAdd(&g_deg[ei[N_EDGES + e]], 1.0f);
}

// ---------------- K2: dinv ---------------------------------------------------
__global__ void k_dinv() {
    int i = blockIdx.x * 256 + threadIdx.x;
    if (i < N_NODES) {
        float d = g_deg[i];
        g_dinv[i] = (d > 0.0f) ? rsqrtf(d) : 0.0f;
    }
}

// ---------------- K3: hs = (x @ Wg) * dinv[row] ------------------------------
__global__ void k_gemm_h(const float* __restrict__ x, const float* __restrict__ Wg) {
    __shared__ float xs[16][TBL];
    int tid = threadIdx.x;
    int col = tid & 127;
    int rh = tid >> 7;
    int rowblk = blockIdx.x * 16;

#pragma unroll
    for (int it = 0; it < 16; it++) {
        int idx = tid + it * 256;
        int r = idx >> 8, k = idx & 255;
        xs[r][k] = x[(size_t)(rowblk + r) * TBL + k];
    }
    __syncthreads();

    float acc[8];
#pragma unroll
    for (int r = 0; r < 8; r++) acc[r] = 0.0f;

#pragma unroll 8
    for (int k = 0; k < TBL; k++) {
        float w = Wg[k * LATENT + col];
#pragma unroll
        for (int r = 0; r < 8; r++) acc[r] += xs[rh * 8 + r][k] * w;
    }

#pragma unroll
    for (int r = 0; r < 8; r++) {
        int node = rowblk + rh * 8 + r;
        g_hs[node * LATENT + col] = acc[r] * g_dinv[node];
    }
}

// ---------------- K4: scatter agg[dst] += hs[src] ----------------------------
__global__ void k_scatter(const int* __restrict__ ei) {
    int t = blockIdx.x * 256 + threadIdx.x;
    int e = t >> 5;
    int lane = t & 31;
    if (e < N_EDGES) {
        int s = ei[e];
        int d = ei[N_EDGES + e];
        const float4 v = *(const float4*)&g_hs[s * LATENT + lane * 4];
        float* p = &g_agg[d * LATENT + lane * 4];
        atomicAdd(p + 0, v.x);
        atomicAdd(p + 1, v.y);
        atomicAdd(p + 2, v.z);
        atomicAdd(p + 3, v.w);
    }
}

// ---------------- K5: z = relu(dinv*agg + bg); Z[b] = z z^T ------------------
__global__ void k_outer(const float* __restrict__ bg) {
    __shared__ float zs[NN][129];
    int b = blockIdx.x;
    int tid = threadIdx.x;

    for (int idx = tid; idx < NN * LATENT; idx += 256) {
        int n = idx >> 7, c = idx & 127;
        int node = b * NN + n;
        float v = g_dinv[node] * g_agg[node * LATENT + c] + bg[c];
        zs[n][c] = (v > 0.0f) ? v : 0.0f;
    }
    __syncthreads();

    int tn = tid >> 4, tm = tid & 15;
    int n0 = tn * 5, m0 = tm * 5;
    float acc[5][5];
#pragma unroll
    for (int i = 0; i < 5; i++)
#pragma unroll
        for (int j = 0; j < 5; j++) acc[i][j] = 0.0f;

#pragma unroll 4
    for (int c = 0; c < LATENT; c++) {
        float zn[5], zm[5];
#pragma unroll
        for (int i = 0; i < 5; i++) { zn[i] = zs[n0 + i][c]; zm[i] = zs[m0 + i][c]; }
#pragma unroll
        for (int i = 0; i < 5; i++)
#pragma unroll
            for (int j = 0; j < 5; j++) acc[i][j] += zn[i] * zm[j];
    }

    float* out = &g_Z[b * N2];
#pragma unroll
    for (int i = 0; i < 5; i++)
#pragma unroll
        for (int j = 0; j < 5; j++)
            out[(n0 + i) * NN + (m0 + j)] = acc[i][j];
}

// ---------------- K5b: transpose+duplicate Z -> ZT ---------------------------
// src [64][K] -> dst [K][128] with dst[k][2b]=dst[k][2b+1]=src[b][k]
__global__ void k_zt() {
    __shared__ float t[64][65];
    int c0 = blockIdx.x * 64;
    int tid = threadIdx.x;
#pragma unroll
    for (int it = 0; it < 16; it++) {
        int idx = tid + it * 256;
        int tb = idx >> 6, tc = idx & 63;
        t[tb][tc] = g_Z[tb * N2 + c0 + tc];
    }
    __syncthreads();
#pragma unroll
    for (int it = 0; it < 16; it++) {
        int idx = tid + it * 256;
        int tb = idx & 63, tc = idx >> 6;
        float v = t[tb][tc];
        *(float2*)&g_ZT[(size_t)(c0 + tc) * 128 + 2 * tb] = make_float2(v, v);
    }
}

// ---------------- K6: big skinny GEMM, pipelined f32x2 -----------------------
// A dup-transposed [K][128] selected in DEVICE code (which: 0=ZT->P1, 1=H1T->P2).
// W [K][N] from harness. Block: 64 rows x 64 cols, 256 threads. grid (N/64, S).
__global__ void __launch_bounds__(256)
k_gemm_big(int which, const float* __restrict__ W,
           int Kper, int N) {
    extern __shared__ float sm[];
    float* As = sm;                       // 2 buffers of KC*128 floats (32KB ea)
    float* Ws = sm + 2 * KC * 128;        // 2 buffers of KC*64  floats (16KB ea)

    const float* __restrict__ Adup = (which == 0) ? g_ZT : g_H1T;
    float* __restrict__ P          = (which == 0) ? g_P1 : g_P2;

    const int tid = threadIdx.x;
    const int jg = tid & 15;              // col group (4 cols)
    const int rg = tid >> 4;              // row group (4 rows)
    const int col0 = blockIdx.x * 64;
    const int kbase = blockIdx.y * Kper;
    const int nch = Kper / KC;

    uint32_t as_u = (uint32_t)__cvta_generic_to_shared(As);
    uint32_t ws_u = (uint32_t)__cvta_generic_to_shared(Ws);

    auto stage = [&](int chunk, int buf) {
        const char* asrc = (const char*)(Adup + (size_t)(kbase + chunk * KC) * 128);
        uint32_t adst = as_u + buf * (KC * 128 * 4);
#pragma unroll
        for (int i = 0; i < 8; i++) {
            int o = (tid + i * 256) * 16;
            cp_async16(adst + o, asrc + o);
        }
        const float* wsrc = W + (size_t)(kbase + chunk * KC) * N + col0;
        uint32_t wdst = ws_u + buf * (KC * 64 * 4);
#pragma unroll
        for (int i = 0; i < 4; i++) {
            int idx = tid + i * 256;
            int k = idx >> 4, xx = idx & 15;
            cp_async16(wdst + (k * 64 + xx * 4) * 4, wsrc + (size_t)k * N + xx * 4);
        }
        cp_commit();
    };

    ull acc[4][2];
#pragma unroll
    for (int i = 0; i < 4; i++) { acc[i][0] = 0ull; acc[i][1] = 0ull; }

    stage(0, 0);

    for (int c = 0; c < nch; c++) {
        if (c + 1 < nch) { stage(c + 1, (c + 1) & 1); cp_wait<1>(); }
        else             { cp_wait<0>(); }
        __syncthreads();

        const float* Ab = As + (c & 1) * (KC * 128);
        const float* Wb = Ws + (c & 1) * (KC * 64);
#pragma unroll 16
        for (int k = 0; k < KC; k++) {
            ulonglong2 a01 = *(const ulonglong2*)(Ab + k * 128 + rg * 8);
            ulonglong2 a23 = *(const ulonglong2*)(Ab + k * 128 + rg * 8 + 4);
            ulonglong2 w   = *(const ulonglong2*)(Wb + k * 64 + jg * 4);
            fma2(acc[0][0], a01.x, w.x); fma2(acc[0][1], a01.x, w.y);
            fma2(acc[1][0], a01.y, w.x); fma2(acc[1][1], a01.y, w.y);
            fma2(acc[2][0], a23.x, w.x); fma2(acc[2][1], a23.x, w.y);
            fma2(acc[3][0], a23.y, w.x); fma2(acc[3][1], a23.y, w.y);
        }
        __syncthreads();
    }

    float* Pp = P + (size_t)blockIdx.y * 64 * N;
#pragma unroll
    for (int i = 0; i < 4; i++) {
        float4 v;
        unpack2(acc[i][0], v.x, v.y);
        unpack2(acc[i][1], v.z, v.w);
        *(float4*)(Pp + (size_t)(rg * 4 + i) * N + col0 + jg * 4) = v;
    }
}

// ---------------- K7: combine GEMM1 partials -> relu -> H1T (dup-T) ----------
__global__ void k_combine1(const float* __restrict__ b1) {
    __shared__ float t[64][65];
    int c0 = blockIdx.x * 64;
    int tid = threadIdx.x;
#pragma unroll
    for (int it = 0; it < 16; it++) {
        int idx = tid + it * 256;
        int tb = idx >> 6, tc = idx & 63;
        float v = g_P1[(size_t)tb * HID + c0 + tc]
                + g_P1[(size_t)N_GRAPHS * HID + (size_t)tb * HID + c0 + tc]
                + b1[c0 + tc];
        t[tb][tc] = (v > 0.0f) ? v : 0.0f;
    }
    __syncthreads();
#pragma unroll
    for (int it = 0; it < 16; it++) {
        int idx = tid + it * 256;
        int tb = idx & 63, tc = idx >> 6;
        float v = t[tb][tc];
        *(float2*)&g_H1T[(size_t)(c0 + tc) * 128 + 2 * tb] = make_float2(v, v);
    }
}

// ---------------- K8: combine GEMM2 partials -> sigmoid -> out ---------------
__global__ void k_combine2(const float* __restrict__ b2, float* __restrict__ out) {
    int i = blockIdx.x * 256 + threadIdx.x;  // 64*6400 = 409600 threads exactly
    const int TOT = N_GRAPHS * N2;
    float v = g_P2[i] + g_P2[i + TOT] + g_P2[i + 2 * TOT] + g_P2[i + 3 * TOT];
    int c = i - (i / N2) * N2;
    v += b2[c];
    out[i] = 1.0f / (1.0f + expf(-v));
}

// ---------------- launch -----------------------------------------------------
extern "C" void kernel_launch(void* const* d_in, const int* in_sizes, int n_in,
                              void* d_out, int out_size) {
    const float* x  = (const float*)d_in[0];
    const int*   ei = (const int*)d_in[1];
    const float* Wg = (const float*)d_in[2];
    const float* bg = (const float*)d_in[3];
    const float* W1 = (const float*)d_in[4];
    const float* b1 = (const float*)d_in[5];
    const float* W2 = (const float*)d_in[6];
    const float* b2 = (const float*)d_in[7];
    float* out = (float*)d_out;

    const int SMEM = (2 * KC * 128 + 2 * KC * 64) * 4;   // 96 KB
    cudaFuncSetAttribute(k_gemm_big, cudaFuncAttributeMaxDynamicSharedMemorySize, SMEM);

    k_zero<<<2580, 256>>>();
    k_deg<<<(N_EDGES + 255) / 256, 256>>>(ei);
    k_dinv<<<(N_NODES + 255) / 256, 256>>>();
    k_gemm_h<<<N_NODES / 16, 256>>>(x, Wg);
    k_scatter<<<(N_EDGES * 32) / 256, 256>>>(ei);
    k_outer<<<N_GRAPHS, 256>>>(bg);
    k_zt<<<N2 / 64, 256>>>();
    k_gemm_big<<<dim3(HID / 64, S1), 256, SMEM>>>(0, W1, N2 / S1, HID);
    k_combine1<<<HID / 64, 256>>>(b1);
    k_gemm_big<<<dim3(N2 / 64, S2), 256, SMEM>>>(1, W2, HID / S2, N2);
    k_combine2<<<(N_GRAPHS * N2) / 256, 256>>>(b2, out);
}

// round 5
// speedup vs baseline: 6.1794x; 1.0529x over previous
#include <cuda_runtime.h>
#include <math.h>
#include <stdint.h>

#define N_NODES 5120
#define TBL 256
#define LATENT 128
#define N_GRAPHS 64
#define N_EDGES 163840
#define NN 80
#define N2 6400
#define HID 12800

#define KC 32          // k-chunk per pipeline stage (48KB smem -> 4 blocks/SM)
#define S1 2           // split-K for GEMM1
#define S2 4           // split-K for GEMM2

typedef unsigned long long ull;

// ---------------- scratch (static device arrays; no cudaMalloc) -------------
__device__ float g_deg[N_NODES];
__device__ float g_dinv[N_NODES];
__device__ float g_hs[N_NODES * LATENT];
__device__ float g_agg[N_NODES * LATENT];
__device__ float g_Z[N_GRAPHS * N2];               // [64][6400]
__device__ float g_ZT[N2 * 128];                    // dup-transposed: [6400][128]
__device__ float g_H1T[HID * 128];                  // dup-transposed: [12800][128]
__device__ float g_P1[S1 * N_GRAPHS * HID];         // GEMM1 partials
__device__ float g_P2[S2 * N_GRAPHS * N2];          // GEMM2 partials

// ---------------- helpers ----------------------------------------------------
__device__ __forceinline__ void unpack2(ull v, float& x, float& y) {
    asm("mov.b64 {%0, %1}, %2;" : "=f"(x), "=f"(y) : "l"(v));
}
__device__ __forceinline__ void fma2(ull& d, ull a, ull b) {
    asm("fma.rn.f32x2 %0, %1, %2, %0;" : "+l"(d) : "l"(a), "l"(b));
}
__device__ __forceinline__ void cp_async16(uint32_t dst, const void* src) {
    asm volatile("cp.async.cg.shared.global [%0], [%1], 16;\n" :: "r"(dst), "l"(src));
}
__device__ __forceinline__ void cp_commit() {
    asm volatile("cp.async.commit_group;\n" ::: "memory");
}
template<int N>
__device__ __forceinline__ void cp_wait() {
    asm volatile("cp.async.wait_group %0;\n" :: "n"(N) : "memory");
}

// ---------------- K0: zero deg + agg ----------------------------------------
__global__ void k_zero() {
    int t = blockIdx.x * blockDim.x + threadIdx.x;
    if (t < N_NODES) g_deg[t] = 0.0f;
    else g_agg[t - N_NODES] = 0.0f;
}

// ---------------- K1: degree counts -----------------------------------------
__global__ void k_deg(const int* __restrict__ ei) {
    int e = blockIdx.x * 256 + threadIdx.x;
    if (e < N_EDGES) atomicAdd(&g_deg[ei[N_EDGES + e]], 1.0f);
}

// ---------------- K2: dinv ---------------------------------------------------
__global__ void k_dinv() {
    int i = blockIdx.x * 256 + threadIdx.x;
    if (i < N_NODES) {
        float d = g_deg[i];
        g_dinv[i] = (d > 0.0f) ? rsqrtf(d) : 0.0f;
    }
}

// ---------------- K3: hs = (x @ Wg) * dinv[row] ------------------------------
__global__ void k_gemm_h(const float* __restrict__ x, const float* __restrict__ Wg) {
    __shared__ float xs[16][TBL];
    int tid = threadIdx.x;
    int col = tid & 127;
    int rh = tid >> 7;
    int rowblk = blockIdx.x * 16;

#pragma unroll
    for (int it = 0; it < 16; it++) {
        int idx = tid + it * 256;
        int r = idx >> 8, k = idx & 255;
        xs[r][k] = x[(size_t)(rowblk + r) * TBL + k];
    }
    __syncthreads();

    float acc[8];
#pragma unroll
    for (int r = 0; r < 8; r++) acc[r] = 0.0f;

#pragma unroll 16
    for (int k = 0; k < TBL; k++) {
        float w = Wg[k * LATENT + col];
#pragma unroll
        for (int r = 0; r < 8; r++) acc[r] += xs[rh * 8 + r][k] * w;
    }

#pragma unroll
    for (int r = 0; r < 8; r++) {
        int node = rowblk + rh * 8 + r;
        g_hs[node * LATENT + col] = acc[r] * g_dinv[node];
    }
}

// ---------------- K4: scatter agg[dst] += hs[src] (vector RED) ---------------
__global__ void k_scatter(const int* __restrict__ ei) {
    int t = blockIdx.x * 256 + threadIdx.x;
    int e = t >> 5;
    int lane = t & 31;
    if (e < N_EDGES) {
        int s = ei[e];
        int d = ei[N_EDGES + e];
        const float4 v = *(const float4*)&g_hs[s * LATENT + lane * 4];
        atomicAdd((float4*)&g_agg[d * LATENT + lane * 4], v);
    }
}

// ---------------- K5: z = relu(dinv*agg + bg); Z[b] = z z^T ------------------
__global__ void k_outer(const float* __restrict__ bg) {
    __shared__ float zs[NN][129];
    int b = blockIdx.x;
    int tid = threadIdx.x;

    for (int idx = tid; idx < NN * LATENT; idx += 256) {
        int n = idx >> 7, c = idx & 127;
        int node = b * NN + n;
        float v = g_dinv[node] * g_agg[node * LATENT + c] + bg[c];
        zs[n][c] = (v > 0.0f) ? v : 0.0f;
    }
    __syncthreads();

    int tn = tid >> 4, tm = tid & 15;
    int n0 = tn * 5, m0 = tm * 5;
    float acc[5][5];
#pragma unroll
    for (int i = 0; i < 5; i++)
#pragma unroll
        for (int j = 0; j < 5; j++) acc[i][j] = 0.0f;

#pragma unroll 4
    for (int c = 0; c < LATENT; c++) {
        float zn[5], zm[5];
#pragma unroll
        for (int i = 0; i < 5; i++) { zn[i] = zs[n0 + i][c]; zm[i] = zs[m0 + i][c]; }
#pragma unroll
        for (int i = 0; i < 5; i++)
#pragma unroll
            for (int j = 0; j < 5; j++) acc[i][j] += zn[i] * zm[j];
    }

    float* out = &g_Z[b * N2];
#pragma unroll
    for (int i = 0; i < 5; i++)
#pragma unroll
        for (int j = 0; j < 5; j++)
            out[(n0 + i) * NN + (m0 + j)] = acc[i][j];
}

// ---------------- K5b: transpose+duplicate Z -> ZT ---------------------------
__global__ void k_zt() {
    __shared__ float t[64][65];
    int c0 = blockIdx.x * 64;
    int tid = threadIdx.x;
#pragma unroll
    for (int it = 0; it < 16; it++) {
        int idx = tid + it * 256;
        int tb = idx >> 6, tc = idx & 63;
        t[tb][tc] = g_Z[tb * N2 + c0 + tc];
    }
    __syncthreads();
#pragma unroll
    for (int it = 0; it < 16; it++) {
        int idx = tid + it * 256;
        int tb = idx & 63, tc = idx >> 6;
        float v = t[tb][tc];
        *(float2*)&g_ZT[(size_t)(c0 + tc) * 128 + 2 * tb] = make_float2(v, v);
    }
}

// ---------------- K6: big skinny GEMM, pipelined f32x2 -----------------------
// A dup-transposed [K][128] selected in DEVICE code (which: 0=ZT->P1, 1=H1T->P2).
// W [K][N] from harness. Block: 64 rows x 64 cols, 256 threads. grid (N/64, S).
__global__ void __launch_bounds__(256, 4)
k_gemm_big(int which, const float* __restrict__ W,
           int Kper, int N) {
    extern __shared__ float sm[];
    float* As = sm;                       // 2 buffers of KC*128 floats (16KB ea)
    float* Ws = sm + 2 * KC * 128;        // 2 buffers of KC*64  floats (8KB ea)

    const float* __restrict__ Adup = (which == 0) ? g_ZT : g_H1T;
    float* __restrict__ P          = (which == 0) ? g_P1 : g_P2;

    const int tid = threadIdx.x;
    const int jg = tid & 15;              // col group (4 cols)
    const int rg = tid >> 4;              // row group (4 row-pairs = 8 rows)
    const int col0 = blockIdx.x * 64;
    const int kbase = blockIdx.y * Kper;
    const int nch = Kper / KC;

    uint32_t as_u = (uint32_t)__cvta_generic_to_shared(As);
    uint32_t ws_u = (uint32_t)__cvta_generic_to_shared(Ws);

    auto stage = [&](int chunk, int buf) {
        const char* asrc = (const char*)(Adup + (size_t)(kbase + chunk * KC) * 128);
        uint32_t adst = as_u + buf * (KC * 128 * 4);
#pragma unroll
        for (int i = 0; i < 4; i++) {
            int o = (tid + i * 256) * 16;
            cp_async16(adst + o, asrc + o);
        }
        const float* wsrc = W + (size_t)(kbase + chunk * KC) * N + col0;
        uint32_t wdst = ws_u + buf * (KC * 64 * 4);
#pragma unroll
        for (int i = 0; i < 2; i++) {
            int idx = tid + i * 256;
            int k = idx >> 4, xx = idx & 15;
            cp_async16(wdst + (k * 64 + xx * 4) * 4, wsrc + (size_t)k * N + xx * 4);
        }
        cp_commit();
    };

    ull acc[4][2];
#pragma unroll
    for (int i = 0; i < 4; i++) { acc[i][0] = 0ull; acc[i][1] = 0ull; }

    stage(0, 0);

    for (int c = 0; c < nch; c++) {
        if (c + 1 < nch) { stage(c + 1, (c + 1) & 1); cp_wait<1>(); }
        else             { cp_wait<0>(); }
        __syncthreads();

        const float* Ab = As + (c & 1) * (KC * 128);
        const float* Wb = Ws + (c & 1) * (KC * 64);
#pragma unroll
        for (int k = 0; k < KC; k++) {
            ulonglong2 a01 = *(const ulonglong2*)(Ab + k * 128 + rg * 8);
            ulonglong2 a23 = *(const ulonglong2*)(Ab + k * 128 + rg * 8 + 4);
            ulonglong2 w   = *(const ulonglong2*)(Wb + k * 64 + jg * 4);
            fma2(acc[0][0], a01.x, w.x); fma2(acc[0][1], a01.x, w.y);
            fma2(acc[1][0], a01.y, w.x); fma2(acc[1][1], a01.y, w.y);
            fma2(acc[2][0], a23.x, w.x); fma2(acc[2][1], a23.x, w.y);
            fma2(acc[3][0], a23.y, w.x); fma2(acc[3][1], a23.y, w.y);
        }
        __syncthreads();
    }

    float* Pp = P + (size_t)blockIdx.y * 64 * N;
#pragma unroll
    for (int i = 0; i < 4; i++) {
        float4 v;
        unpack2(acc[i][0], v.x, v.y);
        unpack2(acc[i][1], v.z, v.w);
        *(float4*)(Pp + (size_t)(rg * 4 + i) * N + col0 + jg * 4) = v;
    }
}

// ---------------- K7: combine GEMM1 partials -> relu -> H1T (dup-T) ----------
__global__ void k_combine1(const float* __restrict__ b1) {
    __shared__ float t[64][65];
    int c0 = blockIdx.x * 64;
    int tid = threadIdx.x;
#pragma unroll
    for (int it = 0; it < 16; it++) {
        int idx = tid + it * 256;
        int tb = idx >> 6, tc = idx & 63;
        float v = g_P1[(size_t)tb * HID + c0 + tc]
                + g_P1[(size_t)N_GRAPHS * HID + (size_t)tb * HID + c0 + tc]
                + b1[c0 + tc];
        t[tb][tc] = (v > 0.0f) ? v : 0.0f;
    }
    __syncthreads();
#pragma unroll
    for (int it = 0; it < 16; it++) {
        int idx = tid + it * 256;
        int tb = idx & 63, tc = idx >> 6;
        float v = t[tb][tc];
        *(float2*)&g_H1T[(size_t)(c0 + tc) * 128 + 2 * tb] = make_float2(v, v);
    }
}

// ---------------- K8: combine GEMM2 partials -> sigmoid -> out ---------------
__global__ void k_combine2(const float* __restrict__ b2, float* __restrict__ out) {
    int i = blockIdx.x * 256 + threadIdx.x;  // 64*6400 = 409600 threads exactly
    const int TOT = N_GRAPHS * N2;
    float v = g_P2[i] + g_P2[i + TOT] + g_P2[i + 2 * TOT] + g_P2[i + 3 * TOT];
    int c = i - (i / N2) * N2;
    v += b2[c];
    out[i] = 1.0f / (1.0f + expf(-v));
}

// ---------------- launch -----------------------------------------------------
extern "C" void kernel_launch(void* const* d_in, const int* in_sizes, int n_in,
                              void* d_out, int out_size) {
    const float* x  = (const float*)d_in[0];
    const int*   ei = (const int*)d_in[1];
    const float* Wg = (const float*)d_in[2];
    const float* bg = (const float*)d_in[3];
    const float* W1 = (const float*)d_in[4];
    const float* b1 = (const float*)d_in[5];
    const float* W2 = (const float*)d_in[6];
    const float* b2 = (const float*)d_in[7];
    float* out = (float*)d_out;

    const int SMEM = (2 * KC * 128 + 2 * KC * 64) * 4;   // 48 KB
    cudaFuncSetAttribute(k_gemm_big, cudaFuncAttributeMaxDynamicSharedMemorySize, SMEM);

    k_zero<<<2580, 256>>>();
    k_deg<<<(N_EDGES + 255) / 256, 256>>>(ei);
    k_dinv<<<(N_NODES + 255) / 256, 256>>>();
    k_gemm_h<<<N_NODES / 16, 256>>>(x, Wg);
    k_scatter<<<(N_EDGES * 32) / 256, 256>>>(ei);
    k_outer<<<N_GRAPHS, 256>>>(bg);
    k_zt<<<N2 / 64, 256>>>();
    k_gemm_big<<<dim3(HID / 64, S1), 256, SMEM>>>(0, W1, N2 / S1, HID);
    k_combine1<<<HID / 64, 256>>>(b1);
    k_gemm_big<<<dim3(N2 / 64, S2), 256, SMEM>>>(1, W2, HID / S2, N2);
    k_combine2<<<(N_GRAPHS * N2) / 256, 256>>>(b2, out);
}

// round 7
// speedup vs baseline: 9.5414x; 1.5441x over previous
#include <cuda_runtime.h>
#include <cuda_bf16.h>
#include <math.h>
#include <stdint.h>

#define N_NODES 5120
#define TBL 256
#define LATENT 128
#define N_GRAPHS 64
#define N_EDGES 163840
#define NN 80
#define N2 6400
#define HID 12800

#define NT 128           // n cols per block tile
#define KC 64            // k per chunk
#define GT 512           // threads per GEMM block
#define S2 2             // split-K for GEMM2

// smem layout (bytes): A tiles padded to 144B rows, W tiles to 272B rows
#define A_STR_B 144
#define W_STR_B 272
#define SM_AH 0
#define SM_AL 9216
#define SM_WH 18432
#define SM_WL 35840
#define SM_TOT 53248

typedef unsigned long long ull;

// ---------------- scratch -----------------------------------------------------
__device__ float g_deg[N_NODES];
__device__ float g_dinv[N_NODES];
__device__ float g_hs[N_NODES * LATENT];
__device__ float g_agg[N_NODES * LATENT];
__device__ float g_Z[N_GRAPHS * N2];
__device__ __align__(256) __nv_bfloat16 g_Zh[N_GRAPHS * N2];
__device__ __align__(256) __nv_bfloat16 g_Zl[N_GRAPHS * N2];
__device__ __align__(256) __nv_bfloat16 g_H1h[N_GRAPHS * HID];
__device__ __align__(256) __nv_bfloat16 g_H1l[N_GRAPHS * HID];
__device__ float g_P2[S2 * N_GRAPHS * N2];

// ---------------- helpers -----------------------------------------------------
__device__ __forceinline__ uint32_t smem_u32(const void* p) {
    uint32_t a;
    asm("{ .reg .u64 t; cvta.to.shared.u64 t, %1; cvt.u32.u64 %0, t; }" : "=r"(a) : "l"(p));
    return a;
}
__device__ __forceinline__ void cp_async16(uint32_t dst, const void* src) {
    asm volatile("cp.async.cg.shared.global [%0], [%1], 16;\n" :: "r"(dst), "l"(src));
}
__device__ __forceinline__ void cp_commit() { asm volatile("cp.async.commit_group;\n" ::: "memory"); }
template<int N> __device__ __forceinline__ void cp_wait() {
    asm volatile("cp.async.wait_group %0;\n" :: "n"(N) : "memory");
}
__device__ __forceinline__ void ldsm_x4(uint32_t* r, uint32_t addr) {
    asm volatile("ldmatrix.sync.aligned.m8n8.x4.shared.b16 {%0,%1,%2,%3}, [%4];"
        : "=r"(r[0]), "=r"(r[1]), "=r"(r[2]), "=r"(r[3]) : "r"(addr));
}
__device__ __forceinline__ void ldsm_x4t(uint32_t* r, uint32_t addr) {
    asm volatile("ldmatrix.sync.aligned.m8n8.x4.trans.shared.b16 {%0,%1,%2,%3}, [%4];"
        : "=r"(r[0]), "=r"(r[1]), "=r"(r[2]), "=r"(r[3]) : "r"(addr));
}
__device__ __forceinline__ void mma_bf16(float* c, const uint32_t* a, const uint32_t* b) {
    asm volatile(
        "mma.sync.aligned.m16n8k16.row.col.f32.bf16.bf16.f32 "
        "{%0,%1,%2,%3}, {%4,%5,%6,%7}, {%8,%9}, {%0,%1,%2,%3};\n"
        : "+f"(c[0]), "+f"(c[1]), "+f"(c[2]), "+f"(c[3])
        : "r"(a[0]), "r"(a[1]), "r"(a[2]), "r"(a[3]), "r"(b[0]), "r"(b[1]));
}
// packed RN bf16x2: low half = bf16(x), high half = bf16(y)
__device__ __forceinline__ uint32_t pack_rn(float x, float y) {
    __nv_bfloat162 t = __float22bfloat162_rn(make_float2(x, y));
    return *(uint32_t*)&t;
}
__device__ __forceinline__ void cvt_hilo(float x, __nv_bfloat16& h, __nv_bfloat16& l) {
    h = __float2bfloat16(x);
    l = __float2bfloat16(x - __bfloat162float(h));
}

// ---------------- small kernels ----------------------------------------------
__global__ void k_zero() {
    int t = blockIdx.x * blockDim.x + threadIdx.x;
    if (t < N_NODES) g_deg[t] = 0.0f;
    else g_agg[t - N_NODES] = 0.0f;
}
__global__ void k_deg(const int* __restrict__ ei) {
    int e = blockIdx.x * 256 + threadIdx.x;
    if (e < N_EDGES) atomicAdd(&g_deg[ei[N_EDGES + e]], 1.0f);
}
__global__ void k_dinv() {
    int i = blockIdx.x * 256 + threadIdx.x;
    if (i < N_NODES) {
        float d = g_deg[i];
        g_dinv[i] = (d > 0.0f) ? rsqrtf(d) : 0.0f;
    }
}
__global__ void k_gemm_h(const float* __restrict__ x, const float* __restrict__ Wg) {
    __shared__ float xs[16][TBL];
    int tid = threadIdx.x;
    int col = tid & 127;
    int rh = tid >> 7;
    int rowblk = blockIdx.x * 16;
#pragma unroll
    for (int it = 0; it < 16; it++) {
        int idx = tid + it * 256;
        int r = idx >> 8, k = idx & 255;
        xs[r][k] = x[(size_t)(rowblk + r) * TBL + k];
    }
    __syncthreads();
    float acc[8];
#pragma unroll
    for (int r = 0; r < 8; r++) acc[r] = 0.0f;
#pragma unroll 16
    for (int k = 0; k < TBL; k++) {
        float w = Wg[k * LATENT + col];
#pragma unroll
        for (int r = 0; r < 8; r++) acc[r] += xs[rh * 8 + r][k] * w;
    }
#pragma unroll
    for (int r = 0; r < 8; r++) {
        int node = rowblk + rh * 8 + r;
        g_hs[node * LATENT + col] = acc[r] * g_dinv[node];
    }
}
__global__ void k_scatter(const int* __restrict__ ei) {
    int t = blockIdx.x * 256 + threadIdx.x;
    int e = t >> 5;
    int lane = t & 31;
    if (e < N_EDGES) {
        int s = ei[e];
        int d = ei[N_EDGES + e];
        const float4 v = *(const float4*)&g_hs[s * LATENT + lane * 4];
        atomicAdd((float4*)&g_agg[d * LATENT + lane * 4], v);
    }
}
__global__ void k_outer(const float* __restrict__ bg) {
    __shared__ float zs[NN][129];
    int b = blockIdx.x;
    int tid = threadIdx.x;
    for (int idx = tid; idx < NN * LATENT; idx += 256) {
        int n = idx >> 7, c = idx & 127;
        int node = b * NN + n;
        float v = g_dinv[node] * g_agg[node * LATENT + c] + bg[c];
        zs[n][c] = (v > 0.0f) ? v : 0.0f;
    }
    __syncthreads();
    int tn = tid >> 4, tm = tid & 15;
    int n0 = tn * 5, m0 = tm * 5;
    float acc[5][5];
#pragma unroll
    for (int i = 0; i < 5; i++)
#pragma unroll
        for (int j = 0; j < 5; j++) acc[i][j] = 0.0f;
#pragma unroll 4
    for (int c = 0; c < LATENT; c++) {
        float zn[5], zm[5];
#pragma unroll
        for (int i = 0; i < 5; i++) { zn[i] = zs[n0 + i][c]; zm[i] = zs[m0 + i][c]; }
#pragma unroll
        for (int i = 0; i < 5; i++)
#pragma unroll
            for (int j = 0; j < 5; j++) acc[i][j] += zn[i] * zm[j];
    }
    float* out = &g_Z[b * N2];
#pragma unroll
    for (int i = 0; i < 5; i++)
#pragma unroll
        for (int j = 0; j < 5; j++)
            out[(n0 + i) * NN + (m0 + j)] = acc[i][j];
}
__global__ void k_prep_z() {
    int i = blockIdx.x * 256 + threadIdx.x;   // 409600 exact
    float v = g_Z[i];
    __nv_bfloat16 h, l;
    cvt_hilo(v, h, l);
    g_Zh[i] = h; g_Zl[i] = l;
}

// ---------------- mma.sync bf16 split-precision GEMM -------------------------
// D[64, NT] block tile. A (hi/lo bf16, row-major [64][Ktot]) via cp.async.
// W fp32 [Ktot][Nout] streamed via regs, converted to hi/lo bf16 in k-major smem.
// which==0: A=Zh/Zl, epilogue = bias+relu -> H1h/H1l (S=1, full K)
// which==1: A=H1h/H1l, epilogue = raw fp32 partials -> g_P2 (S=S2)
__global__ void __launch_bounds__(GT)
k_mma(int which, const float* __restrict__ W, const float* __restrict__ bias,
      int Ktot, int Nout) {
    extern __shared__ char smem[];
    const uint32_t sb = smem_u32(smem);
    const int tid = threadIdx.x;
    const int lane = tid & 31;
    const int wid = tid >> 5;

    const __nv_bfloat16* __restrict__ Ah = (which == 0) ? g_Zh : g_H1h;
    const __nv_bfloat16* __restrict__ Al = (which == 0) ? g_Zl : g_H1l;

    const int col0 = blockIdx.x * NT;
    const int Kper = Ktot / gridDim.y;
    const int kbase = blockIdx.y * Kper;
    const int nch = Kper / KC;

    // ---- W streaming mapping: lane along n (coalesced) ----
    const int n4 = tid & 31;            // float4 position in 128-col tile
    const int kr0 = tid >> 5;           // k row base (0..15), +i*16
    float4 wr[4];
    {
        const float* src = W + (size_t)kbase * Nout + col0 + n4 * 4;
#pragma unroll
        for (int i = 0; i < 4; i++)
            wr[i] = *(const float4*)(src + (size_t)(kr0 + i * 16) * Nout);
    }

    // ---- per-warp mma geometry ----
    const int mstrip = (wid & 3) * 16;  // rows of D
    const int nquad  = (wid >> 2) * 32; // cols within tile
    const int lrow = ((lane >> 3) & 1) * 8 + (lane & 7);
    const int lsel = (lane >> 4) * 8;   // second-tile offset (k for A, n for W)
    const uint32_t aH = sb + SM_AH + (uint32_t)(mstrip + lrow) * A_STR_B + lsel * 2;
    const uint32_t aL = sb + SM_AL + (uint32_t)(mstrip + lrow) * A_STR_B + lsel * 2;
    const uint32_t wH = sb + SM_WH + (uint32_t)lrow * W_STR_B + (uint32_t)(nquad + lsel) * 2;
    const uint32_t wL = sb + SM_WL + (uint32_t)lrow * W_STR_B + (uint32_t)(nquad + lsel) * 2;

    float acc[4][4];
#pragma unroll
    for (int i = 0; i < 4; i++)
#pragma unroll
        for (int j = 0; j < 4; j++) acc[i][j] = 0.0f;

    for (int c = 0; c < nch; c++) {
        const int kb = kbase + c * KC;

        // stage A hi/lo [64][KC] via cp.async (padded rows)
#pragma unroll
        for (int o = 0; o < 2; o++) {
            int idx = tid + o * GT;             // 0..1023
            int sel = idx >> 9;                  // 0=hi 1=lo
            int rem = idx & 511;
            int r = rem >> 3, g = rem & 7;
            const __nv_bfloat16* s = (sel ? Al : Ah) + (size_t)r * Ktot + kb + g * 8;
            cp_async16(sb + (sel ? SM_AL : SM_AH) + r * A_STR_B + g * 16, s);
        }
        cp_commit();

        // convert W regs -> hi/lo bf16, natural k-major layout
#pragma unroll
        for (int i = 0; i < 4; i++) {
            float4 v = wr[i];
            int krow = kr0 + i * 16;
            uint32_t h01 = pack_rn(v.x, v.y);
            uint32_t h23 = pack_rn(v.z, v.w);
            float l0 = v.x - __uint_as_float(h01 << 16);
            float l1 = v.y - __uint_as_float(h01 & 0xffff0000u);
            float l2 = v.z - __uint_as_float(h23 << 16);
            float l3 = v.w - __uint_as_float(h23 & 0xffff0000u);
            uint32_t l01 = pack_rn(l0, l1);
            uint32_t l23 = pack_rn(l2, l3);
            char* ph = smem + SM_WH + krow * W_STR_B + n4 * 8;
            char* pl = smem + SM_WL + krow * W_STR_B + n4 * 8;
            *(uint32_t*)(ph) = h01;  *(uint32_t*)(ph + 4) = h23;
            *(uint32_t*)(pl) = l01;  *(uint32_t*)(pl + 4) = l23;
        }

        cp_wait<0>();
        __syncthreads();

        // prefetch next W chunk (overlaps mma)
        if (c + 1 < nch) {
            const float* src = W + (size_t)(kb + KC) * Nout + col0 + n4 * 4;
#pragma unroll
            for (int i = 0; i < 4; i++)
                wr[i] = *(const float4*)(src + (size_t)(kr0 + i * 16) * Nout);
        }

        // mma over 4 ksteps of 16
#pragma unroll
        for (int ks = 0; ks < 4; ks++) {
            uint32_t ah[4], al[4];
            ldsm_x4(ah, aH + ks * 32);
            ldsm_x4(al, aL + ks * 32);
#pragma unroll
            for (int p = 0; p < 2; p++) {
                uint32_t bh[4], bl[4];
                uint32_t off = (uint32_t)(ks * 16) * W_STR_B + p * 32;
                ldsm_x4t(bh, wH + off);
                ldsm_x4t(bl, wL + off);
#pragma unroll
                for (int q = 0; q < 2; q++) {
                    int nf = p * 2 + q;
                    mma_bf16(acc[nf], ah, bh + q * 2);
                    mma_bf16(acc[nf], ah, bl + q * 2);
                    mma_bf16(acc[nf], al, bh + q * 2);
                }
            }
        }
        __syncthreads();
    }

    // ---- epilogue ----
    const int g = lane >> 2, t4 = lane & 3;
    if (which == 0) {
#pragma unroll
        for (int nf = 0; nf < 4; nf++) {
            int n = col0 + nquad + nf * 8 + t4 * 2;
            float bx = __ldg(&bias[n]), by = __ldg(&bias[n + 1]);
#pragma unroll
            for (int h = 0; h < 2; h++) {
                int m = mstrip + g + h * 8;
                float v0 = fmaxf(acc[nf][h * 2 + 0] + bx, 0.0f);
                float v1 = fmaxf(acc[nf][h * 2 + 1] + by, 0.0f);
                uint32_t hp = pack_rn(v0, v1);
                float l0 = v0 - __uint_as_float(hp << 16);
                float l1 = v1 - __uint_as_float(hp & 0xffff0000u);
                uint32_t lp = pack_rn(l0, l1);
                *(uint32_t*)&g_H1h[(size_t)m * HID + n] = hp;
                *(uint32_t*)&g_H1l[(size_t)m * HID + n] = lp;
            }
        }
    } else {
        float* P = g_P2 + (size_t)blockIdx.y * N_GRAPHS * N2;
#pragma unroll
        for (int nf = 0; nf < 4; nf++) {
            int n = col0 + nquad + nf * 8 + t4 * 2;
#pragma unroll
            for (int h = 0; h < 2; h++) {
                int m = mstrip + g + h * 8;
                *(float2*)&P[(size_t)m * N2 + n] =
                    make_float2(acc[nf][h * 2 + 0], acc[nf][h * 2 + 1]);
            }
        }
    }
}

// ---------------- combine GEMM2 partials -> sigmoid -> out -------------------
__global__ void k_combine2(const float* __restrict__ b2, float* __restrict__ out) {
    int i = blockIdx.x * 256 + threadIdx.x;   // 409600 exact
    const int TOT = N_GRAPHS * N2;
    float v = g_P2[i] + g_P2[i + TOT];
    int c = i - (i / N2) * N2;
    v += b2[c];
    out[i] = 1.0f / (1.0f + expf(-v));
}

// ---------------- launch ------------------------------------------------------
extern "C" void kernel_launch(void* const* d_in, const int* in_sizes, int n_in,
                              void* d_out, int out_size) {
    const float* x  = (const float*)d_in[0];
    const int*   ei = (const int*)d_in[1];
    const float* Wg = (const float*)d_in[2];
    const float* bg = (const float*)d_in[3];
    const float* W1 = (const float*)d_in[4];
    const float* b1 = (const float*)d_in[5];
    const float* W2 = (const float*)d_in[6];
    const float* b2 = (const float*)d_in[7];
    float* out = (float*)d_out;

    cudaFuncSetAttribute(k_mma, cudaFuncAttributeMaxDynamicSharedMemorySize, SM_TOT);

    k_zero<<<2580, 256>>>();
    k_deg<<<(N_EDGES + 255) / 256, 256>>>(ei);
    k_dinv<<<(N_NODES + 255) / 256, 256>>>();
    k_gemm_h<<<N_NODES / 16, 256>>>(x, Wg);
    k_scatter<<<(N_EDGES * 32) / 256, 256>>>(ei);
    k_outer<<<N_GRAPHS, 256>>>(bg);
    k_prep_z<<<(N_GRAPHS * N2) / 256, 256>>>();
    // GEMM1: Ktot=6400, S=1, fused bias+relu+split epilogue -> H1h/H1l
    k_mma<<<dim3(HID / NT, 1), GT, SM_TOT>>>(0, W1, b1, N2, HID);
    // GEMM2: Ktot=12800, S=2 -> partials
    k_mma<<<dim3(N2 / NT, S2), GT, SM_TOT>>>(1, W2, b2, HID, N2);
    k_combine2<<<(N_GRAPHS * N2) / 256, 256>>>(b2, out);
}

// round 8
// speedup vs baseline: 14.6335x; 1.5337x over previous
#include <cuda_runtime.h>
#include <cuda_bf16.h>
#include <math.h>
#include <stdint.h>

#define N_NODES 5120
#define TBL 256
#define LATENT 128
#define N_GRAPHS 64
#define N_EDGES 163840
#define NN 80
#define N2 6400
#define HID 12800

#define NT 128           // n cols per GEMM block tile
#define KC 64            // k per chunk
#define GT 512           // threads per GEMM block
#define S1 4             // split-K for GEMM1
#define S2 8             // split-K for GEMM2

// smem layout (bytes): A tiles padded to 144B rows, W tiles to 272B rows
#define A_STR_B 144
#define W_STR_B 272
#define SM_AH 0
#define SM_AL 9216
#define SM_WH 18432
#define SM_WL 35840
#define SM_TOT 53248

typedef unsigned long long ull;

// ---------------- scratch -----------------------------------------------------
__device__ float g_deg[N_NODES];
__device__ float g_dinv[N_NODES];
__device__ float g_hs[N_NODES * LATENT];
__device__ float g_agg[N_NODES * LATENT];
__device__ __align__(256) __nv_bfloat16 g_Zh[N_GRAPHS * N2];
__device__ __align__(256) __nv_bfloat16 g_Zl[N_GRAPHS * N2];
__device__ __align__(256) __nv_bfloat16 g_H1h[N_GRAPHS * HID];
__device__ __align__(256) __nv_bfloat16 g_H1l[N_GRAPHS * HID];
__device__ float g_P1[S1 * N_GRAPHS * HID];
__device__ float g_P2[S2 * N_GRAPHS * N2];

// ---------------- helpers -----------------------------------------------------
__device__ __forceinline__ uint32_t smem_u32(const void* p) {
    uint32_t a;
    asm("{ .reg .u64 t; cvta.to.shared.u64 t, %1; cvt.u32.u64 %0, t; }" : "=r"(a) : "l"(p));
    return a;
}
__device__ __forceinline__ void cp_async16(uint32_t dst, const void* src) {
    asm volatile("cp.async.cg.shared.global [%0], [%1], 16;\n" :: "r"(dst), "l"(src));
}
__device__ __forceinline__ void cp_commit() { asm volatile("cp.async.commit_group;\n" ::: "memory"); }
template<int N> __device__ __forceinline__ void cp_wait() {
    asm volatile("cp.async.wait_group %0;\n" :: "n"(N) : "memory");
}
__device__ __forceinline__ void ldsm_x4(uint32_t* r, uint32_t addr) {
    asm volatile("ldmatrix.sync.aligned.m8n8.x4.shared.b16 {%0,%1,%2,%3}, [%4];"
        : "=r"(r[0]), "=r"(r[1]), "=r"(r[2]), "=r"(r[3]) : "r"(addr));
}
__device__ __forceinline__ void ldsm_x4t(uint32_t* r, uint32_t addr) {
    asm volatile("ldmatrix.sync.aligned.m8n8.x4.trans.shared.b16 {%0,%1,%2,%3}, [%4];"
        : "=r"(r[0]), "=r"(r[1]), "=r"(r[2]), "=r"(r[3]) : "r"(addr));
}
__device__ __forceinline__ void mma_bf16(float* c, const uint32_t* a, const uint32_t* b) {
    asm volatile(
        "mma.sync.aligned.m16n8k16.row.col.f32.bf16.bf16.f32 "
        "{%0,%1,%2,%3}, {%4,%5,%6,%7}, {%8,%9}, {%0,%1,%2,%3};\n"
        : "+f"(c[0]), "+f"(c[1]), "+f"(c[2]), "+f"(c[3])
        : "r"(a[0]), "r"(a[1]), "r"(a[2]), "r"(a[3]), "r"(b[0]), "r"(b[1]));
}
__device__ __forceinline__ uint32_t pack_rn(float x, float y) {
    __nv_bfloat162 t = __float22bfloat162_rn(make_float2(x, y));
    return *(uint32_t*)&t;
}
__device__ __forceinline__ void cvt_hilo(float x, __nv_bfloat16& h, __nv_bfloat16& l) {
    h = __float2bfloat16(x);
    l = __float2bfloat16(x - __bfloat162float(h));
}

// ---------------- small kernels ----------------------------------------------
__global__ void k_zero() {
    int t = blockIdx.x * blockDim.x + threadIdx.x;
    if (t < N_NODES) g_deg[t] = 0.0f;
    else g_agg[t - N_NODES] = 0.0f;
}
__global__ void k_deg(const int* __restrict__ ei) {
    int e = blockIdx.x * 256 + threadIdx.x;
    if (e < N_EDGES) atomicAdd(&g_deg[ei[N_EDGES + e]], 1.0f);
}
__global__ void k_dinv() {
    int i = blockIdx.x * 256 + threadIdx.x;
    if (i < N_NODES) {
        float d = g_deg[i];
        g_dinv[i] = (d > 0.0f) ? rsqrtf(d) : 0.0f;
    }
}

// ---- hs = (x @ Wg) * dinv[row], cp.async double-buffered Wg chunks ----------
__global__ void k_gemm_h(const float* __restrict__ x, const float* __restrict__ Wg) {
    __shared__ float xs[16][TBL];            // 16 KB
    __shared__ float ws[2][32][LATENT];      // 32 KB
    int tid = threadIdx.x;
    int col = tid & 127;
    int rh = tid >> 7;
    int rowblk = blockIdx.x * 16;

    uint32_t xs_u = smem_u32(&xs[0][0]);
    uint32_t ws_u = smem_u32(&ws[0][0][0]);

    // stage xs (group together with ws chunk 0)
#pragma unroll
    for (int i = 0; i < 4; i++) {
        int idx4 = tid + i * 256;            // 1024 float4s
        int r = idx4 >> 6, k4 = idx4 & 63;
        cp_async16(xs_u + (r * TBL + k4 * 4) * 4,
                   x + (size_t)(rowblk + r) * TBL + k4 * 4);
    }
    auto stage_w = [&](int c) {
#pragma unroll
        for (int i = 0; i < 4; i++) {
            int idx4 = tid + i * 256;        // 1024 float4s
            int k = idx4 >> 5, c4 = idx4 & 31;
            cp_async16(ws_u + ((c & 1) * 32 * LATENT + k * LATENT + c4 * 4) * 4,
                       Wg + (size_t)(c * 32 + k) * LATENT + c4 * 4);
        }
        cp_commit();
    };
    stage_w(0);

    float acc[8];
#pragma unroll
    for (int r = 0; r < 8; r++) acc[r] = 0.0f;

#pragma unroll
    for (int c = 0; c < 8; c++) {
        if (c + 1 < 8) { stage_w(c + 1); cp_wait<1>(); }
        else           { cp_wait<0>(); }
        __syncthreads();
#pragma unroll
        for (int k4 = 0; k4 < 8; k4++) {
            float w0 = ws[c & 1][k4 * 4 + 0][col];
            float w1 = ws[c & 1][k4 * 4 + 1][col];
            float w2 = ws[c & 1][k4 * 4 + 2][col];
            float w3 = ws[c & 1][k4 * 4 + 3][col];
#pragma unroll
            for (int r = 0; r < 8; r++) {
                float4 xv = *(const float4*)&xs[rh * 8 + r][c * 32 + k4 * 4];
                acc[r] += xv.x * w0 + xv.y * w1 + xv.z * w2 + xv.w * w3;
            }
        }
        __syncthreads();
    }

#pragma unroll
    for (int r = 0; r < 8; r++) {
        int node = rowblk + rh * 8 + r;
        g_hs[node * LATENT + col] = acc[r] * g_dinv[node];
    }
}

__global__ void k_scatter(const int* __restrict__ ei) {
    int t = blockIdx.x * 256 + threadIdx.x;
    int e = t >> 5;
    int lane = t & 31;
    if (e < N_EDGES) {
        int s = ei[e];
        int d = ei[N_EDGES + e];
        const float4 v = *(const float4*)&g_hs[s * LATENT + lane * 4];
        atomicAdd((float4*)&g_agg[d * LATENT + lane * 4], v);
    }
}

// ---- z = relu(dinv*agg + bg); Z[b] = z z^T, emitted directly as hi/lo bf16 --
__global__ void k_outer(const float* __restrict__ bg) {
    __shared__ float zs[NN][129];
    int b = blockIdx.x;
    int tid = threadIdx.x;
    for (int idx = tid; idx < NN * LATENT; idx += 256) {
        int n = idx >> 7, c = idx & 127;
        int node = b * NN + n;
        float v = g_dinv[node] * g_agg[node * LATENT + c] + bg[c];
        zs[n][c] = (v > 0.0f) ? v : 0.0f;
    }
    __syncthreads();
    int tn = tid >> 4, tm = tid & 15;
    int n0 = tn * 5, m0 = tm * 5;
    float acc[5][5];
#pragma unroll
    for (int i = 0; i < 5; i++)
#pragma unroll
        for (int j = 0; j < 5; j++) acc[i][j] = 0.0f;
#pragma unroll 4
    for (int c = 0; c < LATENT; c++) {
        float zn[5], zm[5];
#pragma unroll
        for (int i = 0; i < 5; i++) { zn[i] = zs[n0 + i][c]; zm[i] = zs[m0 + i][c]; }
#pragma unroll
        for (int i = 0; i < 5; i++)
#pragma unroll
            for (int j = 0; j < 5; j++) acc[i][j] += zn[i] * zm[j];
    }
    __nv_bfloat16* oh = &g_Zh[b * N2];
    __nv_bfloat16* ol = &g_Zl[b * N2];
#pragma unroll
    for (int i = 0; i < 5; i++)
#pragma unroll
        for (int j = 0; j < 5; j++) {
            __nv_bfloat16 h, l;
            cvt_hilo(acc[i][j], h, l);
            int o = (n0 + i) * NN + (m0 + j);
            oh[o] = h; ol[o] = l;
        }
}

// ---------------- mma.sync bf16 split-precision GEMM -------------------------
// D[64, NT] block tile; split-K along gridDim.y; writes fp32 partials.
// which==0: A=Zh/Zl -> g_P1 ; which==1: A=H1h/H1l -> g_P2
__global__ void __launch_bounds__(GT)
k_mma(int which, const float* __restrict__ W, int Ktot, int Nout) {
    extern __shared__ char smem[];
    const uint32_t sb = smem_u32(smem);
    const int tid = threadIdx.x;
    const int lane = tid & 31;
    const int wid = tid >> 5;

    const __nv_bfloat16* __restrict__ Ah = (which == 0) ? g_Zh : g_H1h;
    const __nv_bfloat16* __restrict__ Al = (which == 0) ? g_Zl : g_H1l;
    float* __restrict__ Pbase = (which == 0) ? g_P1 : g_P2;

    const int col0 = blockIdx.x * NT;
    const int Kper = Ktot / gridDim.y;
    const int kbase = blockIdx.y * Kper;
    const int nch = Kper / KC;

    // W streaming mapping: lane along n (coalesced)
    const int n4 = tid & 31;
    const int kr0 = tid >> 5;
    float4 wr[4];
    {
        const float* src = W + (size_t)kbase * Nout + col0 + n4 * 4;
#pragma unroll
        for (int i = 0; i < 4; i++)
            wr[i] = *(const float4*)(src + (size_t)(kr0 + i * 16) * Nout);
    }

    const int mstrip = (wid & 3) * 16;
    const int nquad  = (wid >> 2) * 32;
    const int lrow = ((lane >> 3) & 1) * 8 + (lane & 7);
    const int lsel = (lane >> 4) * 8;
    const uint32_t aH = sb + SM_AH + (uint32_t)(mstrip + lrow) * A_STR_B + lsel * 2;
    const uint32_t aL = sb + SM_AL + (uint32_t)(mstrip + lrow) * A_STR_B + lsel * 2;
    const uint32_t wH = sb + SM_WH + (uint32_t)lrow * W_STR_B + (uint32_t)(nquad + lsel) * 2;
    const uint32_t wL = sb + SM_WL + (uint32_t)lrow * W_STR_B + (uint32_t)(nquad + lsel) * 2;

    float acc[4][4];
#pragma unroll
    for (int i = 0; i < 4; i++)
#pragma unroll
        for (int j = 0; j < 4; j++) acc[i][j] = 0.0f;

    for (int c = 0; c < nch; c++) {
        const int kb = kbase + c * KC;

        // stage A hi/lo [64][KC]
#pragma unroll
        for (int o = 0; o < 2; o++) {
            int idx = tid + o * GT;
            int sel = idx >> 9;
            int rem = idx & 511;
            int r = rem >> 3, g = rem & 7;
            const __nv_bfloat16* s = (sel ? Al : Ah) + (size_t)r * Ktot + kb + g * 8;
            cp_async16(sb + (sel ? SM_AL : SM_AH) + r * A_STR_B + g * 16, s);
        }
        cp_commit();

        // convert W regs -> hi/lo bf16 k-major
#pragma unroll
        for (int i = 0; i < 4; i++) {
            float4 v = wr[i];
            int krow = kr0 + i * 16;
            uint32_t h01 = pack_rn(v.x, v.y);
            uint32_t h23 = pack_rn(v.z, v.w);
            float l0 = v.x - __uint_as_float(h01 << 16);
            float l1 = v.y - __uint_as_float(h01 & 0xffff0000u);
            float l2 = v.z - __uint_as_float(h23 << 16);
            float l3 = v.w - __uint_as_float(h23 & 0xffff0000u);
            uint32_t l01 = pack_rn(l0, l1);
            uint32_t l23 = pack_rn(l2, l3);
            char* ph = smem + SM_WH + krow * W_STR_B + n4 * 8;
            char* pl = smem + SM_WL + krow * W_STR_B + n4 * 8;
            *(uint32_t*)(ph) = h01;  *(uint32_t*)(ph + 4) = h23;
            *(uint32_t*)(pl) = l01;  *(uint32_t*)(pl + 4) = l23;
        }

        cp_wait<0>();
        __syncthreads();

        // prefetch next W chunk (overlaps mma)
        if (c + 1 < nch) {
            const float* src = W + (size_t)(kb + KC) * Nout + col0 + n4 * 4;
#pragma unroll
            for (int i = 0; i < 4; i++)
                wr[i] = *(const float4*)(src + (size_t)(kr0 + i * 16) * Nout);
        }

#pragma unroll
        for (int ks = 0; ks < 4; ks++) {
            uint32_t ah[4], al[4];
            ldsm_x4(ah, aH + ks * 32);
            ldsm_x4(al, aL + ks * 32);
#pragma unroll
            for (int p = 0; p < 2; p++) {
                uint32_t bh[4], bl[4];
                uint32_t off = (uint32_t)(ks * 16) * W_STR_B + p * 32;
                ldsm_x4t(bh, wH + off);
                ldsm_x4t(bl, wL + off);
#pragma unroll
                for (int q = 0; q < 2; q++) {
                    int nf = p * 2 + q;
                    mma_bf16(acc[nf], ah, bh + q * 2);
                    mma_bf16(acc[nf], ah, bl + q * 2);
                    mma_bf16(acc[nf], al, bh + q * 2);
                }
            }
        }
        __syncthreads();
    }

    // epilogue: raw fp32 partials
    const int g = lane >> 2, t4 = lane & 3;
    float* P = Pbase + (size_t)blockIdx.y * N_GRAPHS * Nout;
#pragma unroll
    for (int nf = 0; nf < 4; nf++) {
        int n = col0 + nquad + nf * 8 + t4 * 2;
#pragma unroll
        for (int h = 0; h < 2; h++) {
            int m = mstrip + g + h * 8;
            *(float2*)&P[(size_t)m * Nout + n] =
                make_float2(acc[nf][h * 2 + 0], acc[nf][h * 2 + 1]);
        }
    }
}

// ---- combine GEMM1 partials -> bias+relu -> H1 hi/lo ------------------------
__global__ void k_combine1(const float* __restrict__ b1) {
    int i = blockIdx.x * 512 + threadIdx.x;   // 819200 exact (1600 blocks)
    const int TOT = N_GRAPHS * HID;
    float v = g_P1[i] + g_P1[i + TOT] + g_P1[i + 2 * TOT] + g_P1[i + 3 * TOT];
    int col = i - (i / HID) * HID;
    v += b1[col];
    v = (v > 0.0f) ? v : 0.0f;
    __nv_bfloat16 h, l;
    cvt_hilo(v, h, l);
    g_H1h[i] = h; g_H1l[i] = l;
}

// ---- combine GEMM2 partials -> sigmoid -> out -------------------------------
__global__ void k_combine2(const float* __restrict__ b2, float* __restrict__ out) {
    int i = blockIdx.x * 256 + threadIdx.x;   // 409600 exact
    const int TOT = N_GRAPHS * N2;
    float v = 0.0f;
#pragma unroll
    for (int s = 0; s < S2; s++) v += g_P2[i + s * TOT];
    int c = i - (i / N2) * N2;
    v += b2[c];
    out[i] = 1.0f / (1.0f + expf(-v));
}

// ---------------- launch ------------------------------------------------------
extern "C" void kernel_launch(void* const* d_in, const int* in_sizes, int n_in,
                              void* d_out, int out_size) {
    const float* x  = (const float*)d_in[0];
    const int*   ei = (const int*)d_in[1];
    const float* Wg = (const float*)d_in[2];
    const float* bg = (const float*)d_in[3];
    const float* W1 = (const float*)d_in[4];
    const float* b1 = (const float*)d_in[5];
    const float* W2 = (const float*)d_in[6];
    const float* b2 = (const float*)d_in[7];
    float* out = (float*)d_out;

    cudaFuncSetAttribute(k_mma, cudaFuncAttributeMaxDynamicSharedMemorySize, SM_TOT);

    k_zero<<<2580, 256>>>();
    k_deg<<<(N_EDGES + 255) / 256, 256>>>(ei);
    k_dinv<<<(N_NODES + 255) / 256, 256>>>();
    k_gemm_h<<<N_NODES / 16, 256>>>(x, Wg);
    k_scatter<<<(N_EDGES * 32) / 256, 256>>>(ei);
    k_outer<<<N_GRAPHS, 256>>>(bg);
    // GEMM1: Ktot=6400, S1=4 -> 400 blocks
    k_mma<<<dim3(HID / NT, S1), GT, SM_TOT>>>(0, W1, N2, HID);
    k_combine1<<<(N_GRAPHS * HID) / 512, 512>>>(b1);
    // GEMM2: Ktot=12800, S2=8 -> 400 blocks
    k_mma<<<dim3(N2 / NT, S2), GT, SM_TOT>>>(1, W2, HID, N2);
    k_combine2<<<(N_GRAPHS * N2) / 256, 256>>>(b2, out);
}

// round 9
// speedup vs baseline: 14.7291x; 1.0065x over previous
#include <cuda_runtime.h>
#include <cuda_bf16.h>
#include <math.h>
#include <stdint.h>

#define N_NODES 5120
#define TBL 256
#define LATENT 128
#define N_GRAPHS 64
#define N_EDGES 163840
#define NN 80
#define N2 6400
#define HID 12800

#define NT 64            // n cols per GEMM block tile
#define KC 64            // k per chunk
#define GT 256           // threads per GEMM block
#define S1 4             // split-K for GEMM1 (800 blocks)
#define S2 8             // split-K for GEMM2 (800 blocks)

// smem layout (bytes): A rows padded to 144B, W rows padded to 144B (64 cols)
#define A_STR_B 144
#define W_STR_B 144
#define A_BUF_B 9216                 // 64 rows * 144B, one of hi/lo
#define SM_A 0                       // A: 2 bufs x (hi 9216 + lo 9216) = 36864
#define SM_WH 36864                  // W hi: 64 k-rows * 144B = 9216
#define SM_WL 46080                  // W lo
#define SM_TOT 55296

typedef unsigned long long ull;

// ---------------- scratch -----------------------------------------------------
__device__ float g_deg[N_NODES];
__device__ float g_dinv[N_NODES];
__device__ float g_hs[N_NODES * LATENT];
__device__ float g_agg[N_NODES * LATENT];
__device__ __align__(256) __nv_bfloat16 g_Zh[N_GRAPHS * N2];
__device__ __align__(256) __nv_bfloat16 g_Zl[N_GRAPHS * N2];
__device__ __align__(256) __nv_bfloat16 g_H1h[N_GRAPHS * HID];
__device__ __align__(256) __nv_bfloat16 g_H1l[N_GRAPHS * HID];
__device__ float g_P1[S1 * N_GRAPHS * HID];
__device__ float g_P2[S2 * N_GRAPHS * N2];

// ---------------- helpers -----------------------------------------------------
__device__ __forceinline__ uint32_t smem_u32(const void* p) {
    uint32_t a;
    asm("{ .reg .u64 t; cvta.to.shared.u64 t, %1; cvt.u32.u64 %0, t; }" : "=r"(a) : "l"(p));
    return a;
}
__device__ __forceinline__ void cp_async16(uint32_t dst, const void* src) {
    asm volatile("cp.async.cg.shared.global [%0], [%1], 16;\n" :: "r"(dst), "l"(src));
}
__device__ __forceinline__ void cp_commit() { asm volatile("cp.async.commit_group;\n" ::: "memory"); }
template<int N> __device__ __forceinline__ void cp_wait() {
    asm volatile("cp.async.wait_group %0;\n" :: "n"(N) : "memory");
}
__device__ __forceinline__ void ldsm_x4(uint32_t* r, uint32_t addr) {
    asm volatile("ldmatrix.sync.aligned.m8n8.x4.shared.b16 {%0,%1,%2,%3}, [%4];"
        : "=r"(r[0]), "=r"(r[1]), "=r"(r[2]), "=r"(r[3]) : "r"(addr));
}
__device__ __forceinline__ void ldsm_x4t(uint32_t* r, uint32_t addr) {
    asm volatile("ldmatrix.sync.aligned.m8n8.x4.trans.shared.b16 {%0,%1,%2,%3}, [%4];"
        : "=r"(r[0]), "=r"(r[1]), "=r"(r[2]), "=r"(r[3]) : "r"(addr));
}
__device__ __forceinline__ void mma_bf16(float* c, const uint32_t* a, const uint32_t* b) {
    asm volatile(
        "mma.sync.aligned.m16n8k16.row.col.f32.bf16.bf16.f32 "
        "{%0,%1,%2,%3}, {%4,%5,%6,%7}, {%8,%9}, {%0,%1,%2,%3};\n"
        : "+f"(c[0]), "+f"(c[1]), "+f"(c[2]), "+f"(c[3])
        : "r"(a[0]), "r"(a[1]), "r"(a[2]), "r"(a[3]), "r"(b[0]), "r"(b[1]));
}
__device__ __forceinline__ uint32_t pack_rn(float x, float y) {
    __nv_bfloat162 t = __float22bfloat162_rn(make_float2(x, y));
    return *(uint32_t*)&t;
}
__device__ __forceinline__ void cvt_hilo(float x, __nv_bfloat16& h, __nv_bfloat16& l) {
    h = __float2bfloat16(x);
    l = __float2bfloat16(x - __bfloat162float(h));
}

// ---------------- small kernels ----------------------------------------------
__global__ void k_zero() {
    int t = blockIdx.x * blockDim.x + threadIdx.x;
    if (t < N_NODES) g_deg[t] = 0.0f;
    else g_agg[t - N_NODES] = 0.0f;
}
__global__ void k_deg(const int* __restrict__ ei) {
    int e = blockIdx.x * 256 + threadIdx.x;
    if (e < N_EDGES) atomicAdd(&g_deg[ei[N_EDGES + e]], 1.0f);
}
__global__ void k_dinv() {
    int i = blockIdx.x * 256 + threadIdx.x;
    if (i < N_NODES) {
        float d = g_deg[i];
        g_dinv[i] = (d > 0.0f) ? rsqrtf(d) : 0.0f;
    }
}

// ---- hs = (x @ Wg) * dinv[row] ----------------------------------------------
__global__ void k_gemm_h(const float* __restrict__ x, const float* __restrict__ Wg) {
    __shared__ float xs[16][TBL];
    __shared__ float ws[2][32][LATENT];
    int tid = threadIdx.x;
    int col = tid & 127;
    int rh = tid >> 7;
    int rowblk = blockIdx.x * 16;

    uint32_t xs_u = smem_u32(&xs[0][0]);
    uint32_t ws_u = smem_u32(&ws[0][0][0]);

#pragma unroll
    for (int i = 0; i < 4; i++) {
        int idx4 = tid + i * 256;
        int r = idx4 >> 6, k4 = idx4 & 63;
        cp_async16(xs_u + (r * TBL + k4 * 4) * 4,
                   x + (size_t)(rowblk + r) * TBL + k4 * 4);
    }
    auto stage_w = [&](int c) {
#pragma unroll
        for (int i = 0; i < 4; i++) {
            int idx4 = tid + i * 256;
            int k = idx4 >> 5, c4 = idx4 & 31;
            cp_async16(ws_u + ((c & 1) * 32 * LATENT + k * LATENT + c4 * 4) * 4,
                       Wg + (size_t)(c * 32 + k) * LATENT + c4 * 4);
        }
        cp_commit();
    };
    stage_w(0);

    float acc[8];
#pragma unroll
    for (int r = 0; r < 8; r++) acc[r] = 0.0f;

#pragma unroll
    for (int c = 0; c < 8; c++) {
        if (c + 1 < 8) { stage_w(c + 1); cp_wait<1>(); }
        else           { cp_wait<0>(); }
        __syncthreads();
#pragma unroll
        for (int k4 = 0; k4 < 8; k4++) {
            float w0 = ws[c & 1][k4 * 4 + 0][col];
            float w1 = ws[c & 1][k4 * 4 + 1][col];
            float w2 = ws[c & 1][k4 * 4 + 2][col];
            float w3 = ws[c & 1][k4 * 4 + 3][col];
#pragma unroll
            for (int r = 0; r < 8; r++) {
                float4 xv = *(const float4*)&xs[rh * 8 + r][c * 32 + k4 * 4];
                acc[r] += xv.x * w0 + xv.y * w1 + xv.z * w2 + xv.w * w3;
            }
        }
        __syncthreads();
    }

#pragma unroll
    for (int r = 0; r < 8; r++) {
        int node = rowblk + rh * 8 + r;
        g_hs[node * LATENT + col] = acc[r] * g_dinv[node];
    }
}

__global__ void k_scatter(const int* __restrict__ ei) {
    int t = blockIdx.x * 256 + threadIdx.x;
    int e = t >> 5;
    int lane = t & 31;
    if (e < N_EDGES) {
        int s = ei[e];
        int d = ei[N_EDGES + e];
        const float4 v = *(const float4*)&g_hs[s * LATENT + lane * 4];
        atomicAdd((float4*)&g_agg[d * LATENT + lane * 4], v);
    }
}

// ---- z = relu(dinv*agg + bg); Z[b] = z z^T -> hi/lo bf16 --------------------
__global__ void k_outer(const float* __restrict__ bg) {
    __shared__ float zs[NN][129];
    int b = blockIdx.x;
    int tid = threadIdx.x;
    for (int idx = tid; idx < NN * LATENT; idx += 256) {
        int n = idx >> 7, c = idx & 127;
        int node = b * NN + n;
        float v = g_dinv[node] * g_agg[node * LATENT + c] + bg[c];
        zs[n][c] = (v > 0.0f) ? v : 0.0f;
    }
    __syncthreads();
    int tn = tid >> 4, tm = tid & 15;
    int n0 = tn * 5, m0 = tm * 5;
    float acc[5][5];
#pragma unroll
    for (int i = 0; i < 5; i++)
#pragma unroll
        for (int j = 0; j < 5; j++) acc[i][j] = 0.0f;
#pragma unroll 4
    for (int c = 0; c < LATENT; c++) {
        float zn[5], zm[5];
#pragma unroll
        for (int i = 0; i < 5; i++) { zn[i] = zs[n0 + i][c]; zm[i] = zs[m0 + i][c]; }
#pragma unroll
        for (int i = 0; i < 5; i++)
#pragma unroll
            for (int j = 0; j < 5; j++) acc[i][j] += zn[i] * zm[j];
    }
    __nv_bfloat16* oh = &g_Zh[b * N2];
    __nv_bfloat16* ol = &g_Zl[b * N2];
#pragma unroll
    for (int i = 0; i < 5; i++)
#pragma unroll
        for (int j = 0; j < 5; j++) {
            __nv_bfloat16 h, l;
            cvt_hilo(acc[i][j], h, l);
            int o = (n0 + i) * NN + (m0 + j);
            oh[o] = h; ol[o] = l;
        }
}

// ---------------- mma.sync bf16 split-precision GEMM -------------------------
// 256 threads, D[64 x 64] tile, A double-buffered, W streamed via regs.
// which==0: A=Zh/Zl -> g_P1 ; which==1: A=H1h/H1l -> g_P2
__global__ void __launch_bounds__(GT, 2)
k_mma(int which, const float* __restrict__ W, int Ktot, int Nout) {
    extern __shared__ char smem[];
    const uint32_t sb = smem_u32(smem);
    const int tid = threadIdx.x;
    const int lane = tid & 31;
    const int wid = tid >> 5;

    const __nv_bfloat16* __restrict__ Ah = (which == 0) ? g_Zh : g_H1h;
    const __nv_bfloat16* __restrict__ Al = (which == 0) ? g_Zl : g_H1l;
    float* __restrict__ Pbase = (which == 0) ? g_P1 : g_P2;

    const int col0 = blockIdx.x * NT;
    const int Kper = Ktot / gridDim.y;
    const int kbase = blockIdx.y * Kper;
    const int nch = Kper / KC;

    // W streaming: n4 = float4 col (16 per 64-col tile), kr0 = k row base
    const int n4 = tid & 15;
    const int kr0 = tid >> 4;          // 0..15, +i*16
    float4 wr[4];
    {
        const float* src = W + (size_t)kbase * Nout + col0 + n4 * 4;
#pragma unroll
        for (int i = 0; i < 4; i++)
            wr[i] = *(const float4*)(src + (size_t)(kr0 + i * 16) * Nout);
    }

    // warp geometry: 4 m-strips x 2 n-quads
    const int mstrip = (wid & 3) * 16;
    const int nquad  = (wid >> 2) * 32;
    const int lrow = ((lane >> 3) & 1) * 8 + (lane & 7);
    const int lsel = (lane >> 4) * 8;
    const uint32_t aOff = (uint32_t)(mstrip + lrow) * A_STR_B + lsel * 2;
    const uint32_t wH = sb + SM_WH + (uint32_t)lrow * W_STR_B + (uint32_t)(nquad + lsel) * 2;
    const uint32_t wL = sb + SM_WL + (uint32_t)lrow * W_STR_B + (uint32_t)(nquad + lsel) * 2;

    // A staging: idx 0..1023 -> sel(hi/lo), row, 16B group
    auto stage_a = [&](int c, int buf) {
        const int kb = kbase + c * KC;
        const uint32_t base = sb + SM_A + (uint32_t)buf * (2 * A_BUF_B);
#pragma unroll
        for (int o = 0; o < 4; o++) {
            int idx = tid + o * GT;
            int sel = idx >> 9;
            int rem = idx & 511;
            int r = rem >> 3, g = rem & 7;
            const __nv_bfloat16* s = (sel ? Al : Ah) + (size_t)r * Ktot + kb + g * 8;
            cp_async16(base + sel * A_BUF_B + r * A_STR_B + g * 16, s);
        }
        cp_commit();
    };

    float acc[4][4];
#pragma unroll
    for (int i = 0; i < 4; i++)
#pragma unroll
        for (int j = 0; j < 4; j++) acc[i][j] = 0.0f;

    stage_a(0, 0);

    for (int c = 0; c < nch; c++) {
        // prefetch A(c+1) into alternate buffer (overlaps convert + mma)
        if (c + 1 < nch) stage_a(c + 1, (c + 1) & 1);

        // convert W(c) regs -> hi/lo bf16 k-major smem (prev mma done reading)
#pragma unroll
        for (int i = 0; i < 4; i++) {
            float4 v = wr[i];
            int krow = kr0 + i * 16;
            uint32_t h01 = pack_rn(v.x, v.y);
            uint32_t h23 = pack_rn(v.z, v.w);
            float l0 = v.x - __uint_as_float(h01 << 16);
            float l1 = v.y - __uint_as_float(h01 & 0xffff0000u);
            float l2 = v.z - __uint_as_float(h23 << 16);
            float l3 = v.w - __uint_as_float(h23 & 0xffff0000u);
            uint32_t l01 = pack_rn(l0, l1);
            uint32_t l23 = pack_rn(l2, l3);
            char* ph = smem + SM_WH + krow * W_STR_B + n4 * 8;
            char* pl = smem + SM_WL + krow * W_STR_B + n4 * 8;
            *(uint32_t*)(ph) = h01;  *(uint32_t*)(ph + 4) = h23;
            *(uint32_t*)(pl) = l01;  *(uint32_t*)(pl + 4) = l23;
        }

        // wait A(c) (A(c+1) may remain in flight)
        if (c + 1 < nch) cp_wait<1>();
        else             cp_wait<0>();
        __syncthreads();

        // prefetch next W chunk (overlaps mma)
        if (c + 1 < nch) {
            const float* src = W + (size_t)(kbase + (c + 1) * KC) * Nout + col0 + n4 * 4;
#pragma unroll
            for (int i = 0; i < 4; i++)
                wr[i] = *(const float4*)(src + (size_t)(kr0 + i * 16) * Nout);
        }

        const uint32_t aB = sb + SM_A + (uint32_t)(c & 1) * (2 * A_BUF_B);
#pragma unroll
        for (int ks = 0; ks < 4; ks++) {
            uint32_t ah[4], al[4];
            ldsm_x4(ah, aB + aOff + ks * 32);
            ldsm_x4(al, aB + A_BUF_B + aOff + ks * 32);
#pragma unroll
            for (int p = 0; p < 2; p++) {
                uint32_t bh[4], bl[4];
                uint32_t off = (uint32_t)(ks * 16) * W_STR_B + p * 32;
                ldsm_x4t(bh, wH + off);
                ldsm_x4t(bl, wL + off);
#pragma unroll
                for (int q = 0; q < 2; q++) {
                    int nf = p * 2 + q;
                    mma_bf16(acc[nf], ah, bh + q * 2);
                    mma_bf16(acc[nf], ah, bl + q * 2);
                    mma_bf16(acc[nf], al, bh + q * 2);
                }
            }
        }
        __syncthreads();
    }

    // epilogue: raw fp32 partials
    const int g = lane >> 2, t4 = lane & 3;
    float* P = Pbase + (size_t)blockIdx.y * N_GRAPHS * Nout;
#pragma unroll
    for (int nf = 0; nf < 4; nf++) {
        int n = col0 + nquad + nf * 8 + t4 * 2;
#pragma unroll
        for (int h = 0; h < 2; h++) {
            int m = mstrip + g + h * 8;
            *(float2*)&P[(size_t)m * Nout + n] =
                make_float2(acc[nf][h * 2 + 0], acc[nf][h * 2 + 1]);
        }
    }
}

// ---- combine GEMM1 partials -> bias+relu -> H1 hi/lo ------------------------
__global__ void k_combine1(const float* __restrict__ b1) {
    int i = blockIdx.x * 512 + threadIdx.x;   // 819200 exact (1600 blocks)
    const int TOT = N_GRAPHS * HID;
    float v = 0.0f;
#pragma unroll
    for (int s = 0; s < S1; s++) v += g_P1[i + s * TOT];
    int col = i - (i / HID) * HID;
    v += b1[col];
    v = (v > 0.0f) ? v : 0.0f;
    __nv_bfloat16 h, l;
    cvt_hilo(v, h, l);
    g_H1h[i] = h; g_H1l[i] = l;
}

// ---- combine GEMM2 partials -> sigmoid -> out -------------------------------
__global__ void k_combine2(const float* __restrict__ b2, float* __restrict__ out) {
    int i = blockIdx.x * 256 + threadIdx.x;   // 409600 exact
    const int TOT = N_GRAPHS * N2;
    float v = 0.0f;
#pragma unroll
    for (int s = 0; s < S2; s++) v += g_P2[i + s * TOT];
    int c = i - (i / N2) * N2;
    v += b2[c];
    out[i] = 1.0f / (1.0f + expf(-v));
}

// ---------------- launch ------------------------------------------------------
extern "C" void kernel_launch(void* const* d_in, const int* in_sizes, int n_in,
                              void* d_out, int out_size) {
    const float* x  = (const float*)d_in[0];
    const int*   ei = (const int*)d_in[1];
    const float* Wg = (const float*)d_in[2];
    const float* bg = (const float*)d_in[3];
    const float* W1 = (const float*)d_in[4];
    const float* b1 = (const float*)d_in[5];
    const float* W2 = (const float*)d_in[6];
    const float* b2 = (const float*)d_in[7];
    float* out = (float*)d_out;

    cudaFuncSetAttribute(k_mma, cudaFuncAttributeMaxDynamicSharedMemorySize, SM_TOT);

    k_zero<<<2580, 256>>>();
    k_deg<<<(N_EDGES + 255) / 256, 256>>>(ei);
    k_dinv<<<(N_NODES + 255) / 256, 256>>>();
    k_gemm_h<<<N_NODES / 16, 256>>>(x, Wg);
    k_scatter<<<(N_EDGES * 32) / 256, 256>>>(ei);
    k_outer<<<N_GRAPHS, 256>>>(bg);
    // GEMM1: 200 col tiles x S1=4 = 800 blocks, Kper=1600
    k_mma<<<dim3(HID / NT, S1), GT, SM_TOT>>>(0, W1, N2, HID);
    k_combine1<<<(N_GRAPHS * HID) / 512, 512>>>(b1);
    // GEMM2: 100 col tiles x S2=8 = 800 blocks, Kper=1600
    k_mma<<<dim3(N2 / NT, S2), GT, SM_TOT>>>(1, W2, HID, N2);
    k_combine2<<<(N_GRAPHS * N2) / 256, 256>>>(b2, out);
}

// round 11
// speedup vs baseline: 15.5065x; 1.0528x over previous
#include <cuda_runtime.h>
#include <cuda_bf16.h>
#include <math.h>
#include <stdint.h>

#define N_NODES 5120
#define TBL 256
#define LATENT 128
#define N_GRAPHS 64
#define N_EDGES 163840
#define NN 80
#define N2 6400
#define HID 12800

#define NT 64            // n cols per GEMM block tile
#define KC 64            // k per chunk
#define GT 256           // threads per GEMM block
#define S1 4             // split-K GEMM1 (800 blocks)
#define S2 8             // split-K GEMM2 (800 blocks)

// smem layout (bytes): A rows padded to 144B, W rows padded to 144B (64 cols)
#define A_STR_B 144
#define W_STR_B 144
#define A_BUF_B 9216                 // 64 rows * 144B, one of hi/lo
#define SM_A 0                       // A: 2 bufs x (hi 9216 + lo 9216) = 36864
#define SM_WH 36864                  // W hi: 64 k-rows * 144B = 9216
#define SM_WL 46080                  // W lo
#define SM_TOT 55296

typedef unsigned long long ull;

// ---------------- scratch -----------------------------------------------------
__device__ float g_deg[N_NODES];
__device__ float g_dinv[N_NODES];
__device__ float g_hs[N_NODES * LATENT];
__device__ float g_agg[N_NODES * LATENT];
__device__ __align__(256) __nv_bfloat16 g_Zh[N_GRAPHS * N2];
__device__ __align__(256) __nv_bfloat16 g_Zl[N_GRAPHS * N2];
__device__ __align__(256) __nv_bfloat16 g_H1h[N_GRAPHS * HID];
__device__ __align__(256) __nv_bfloat16 g_H1l[N_GRAPHS * HID];
__device__ float g_P1[S1 * N_GRAPHS * HID];
__device__ float g_P2[S2 * N_GRAPHS * N2];

// ---------------- helpers -----------------------------------------------------
__device__ __forceinline__ uint32_t smem_u32(const void* p) {
    uint32_t a;
    asm("{ .reg .u64 t; cvta.to.shared.u64 t, %1; cvt.u32.u64 %0, t; }" : "=r"(a) : "l"(p));
    return a;
}
__device__ __forceinline__ void cp_async16(uint32_t dst, const void* src) {
    asm volatile("cp.async.cg.shared.global [%0], [%1], 16;\n" :: "r"(dst), "l"(src));
}
__device__ __forceinline__ void cp_commit() { asm volatile("cp.async.commit_group;\n" ::: "memory"); }
template<int N> __device__ __forceinline__ void cp_wait() {
    asm volatile("cp.async.wait_group %0;\n" :: "n"(N) : "memory");
}
__device__ __forceinline__ void ldsm_x4(uint32_t* r, uint32_t addr) {
    asm volatile("ldmatrix.sync.aligned.m8n8.x4.shared.b16 {%0,%1,%2,%3}, [%4];"
        : "=r"(r[0]), "=r"(r[1]), "=r"(r[2]), "=r"(r[3]) : "r"(addr));
}
__device__ __forceinline__ void ldsm_x4t(uint32_t* r, uint32_t addr) {
    asm volatile("ldmatrix.sync.aligned.m8n8.x4.trans.shared.b16 {%0,%1,%2,%3}, [%4];"
        : "=r"(r[0]), "=r"(r[1]), "=r"(r[2]), "=r"(r[3]) : "r"(addr));
}
__device__ __forceinline__ void mma_bf16(float* c, const uint32_t* a, const uint32_t* b) {
    asm volatile(
        "mma.sync.aligned.m16n8k16.row.col.f32.bf16.bf16.f32 "
        "{%0,%1,%2,%3}, {%4,%5,%6,%7}, {%8,%9}, {%0,%1,%2,%3};\n"
        : "+f"(c[0]), "+f"(c[1]), "+f"(c[2]), "+f"(c[3])
        : "r"(a[0]), "r"(a[1]), "r"(a[2]), "r"(a[3]), "r"(b[0]), "r"(b[1]));
}
__device__ __forceinline__ uint32_t pack_rn(float x, float y) {
    __nv_bfloat162 t = __float22bfloat162_rn(make_float2(x, y));
    return *(uint32_t*)&t;
}
__device__ __forceinline__ void cvt_hilo(float x, __nv_bfloat16& h, __nv_bfloat16& l) {
    h = __float2bfloat16(x);
    l = __float2bfloat16(x - __bfloat162float(h));
}

// ---------------- small kernels ----------------------------------------------
__global__ void k_zero() {
    int t = blockIdx.x * blockDim.x + threadIdx.x;
    if (t < N_NODES) g_deg[t] = 0.0f;
    else g_agg[t - N_NODES] = 0.0f;
}
__global__ void k_deg(const int* __restrict__ ei) {
    int e = blockIdx.x * 256 + threadIdx.x;
    if (e < N_EDGES) atomicAdd(&g_deg[ei[N_EDGES + e]], 1.0f);
}

// ---- hs = (x @ Wg) * dinv[row]; also emits g_dinv ---------------------------
__global__ void k_gemm_h(const float* __restrict__ x, const float* __restrict__ Wg) {
    __shared__ float xs[16][TBL];          // 16 KB
    __shared__ float ws[2][16][LATENT];    // 16 KB
    int tid = threadIdx.x;
    int col = tid & 127;
    int rh = tid >> 7;
    int rowblk = blockIdx.x * 16;

    uint32_t xs_u = smem_u32(&xs[0][0]);
    uint32_t ws_u = smem_u32(&ws[0][0][0]);

#pragma unroll
    for (int i = 0; i < 4; i++) {
        int idx4 = tid + i * 256;
        int r = idx4 >> 6, k4 = idx4 & 63;
        cp_async16(xs_u + (r * TBL + k4 * 4) * 4,
                   x + (size_t)(rowblk + r) * TBL + k4 * 4);
    }
    auto stage_w = [&](int c) {
#pragma unroll
        for (int i = 0; i < 2; i++) {
            int idx4 = tid + i * 256;            // 0..511
            int k = idx4 >> 5, c4 = idx4 & 31;
            cp_async16(ws_u + ((c & 1) * 16 * LATENT + k * LATENT + c4 * 4) * 4,
                       Wg + (size_t)(c * 16 + k) * LATENT + c4 * 4);
        }
        cp_commit();
    };
    stage_w(0);

    float acc[8];
#pragma unroll
    for (int r = 0; r < 8; r++) acc[r] = 0.0f;

#pragma unroll
    for (int c = 0; c < 16; c++) {
        if (c + 1 < 16) { stage_w(c + 1); cp_wait<1>(); }
        else            { cp_wait<0>(); }
        __syncthreads();
#pragma unroll
        for (int k4 = 0; k4 < 4; k4++) {
            float w0 = ws[c & 1][k4 * 4 + 0][col];
            float w1 = ws[c & 1][k4 * 4 + 1][col];
            float w2 = ws[c & 1][k4 * 4 + 2][col];
            float w3 = ws[c & 1][k4 * 4 + 3][col];
#pragma unroll
            for (int r = 0; r < 8; r++) {
                float4 xv = *(const float4*)&xs[rh * 8 + r][c * 16 + k4 * 4];
                acc[r] += xv.x * w0 + xv.y * w1 + xv.z * w2 + xv.w * w3;
            }
        }
        __syncthreads();
    }

#pragma unroll
    for (int r = 0; r < 8; r++) {
        int node = rowblk + rh * 8 + r;
        float d = g_deg[node];
        float di = (d > 0.0f) ? rsqrtf(d) : 0.0f;
        g_hs[node * LATENT + col] = acc[r] * di;
        if (col == 0) g_dinv[node] = di;
    }
}

__global__ void k_scatter(const int* __restrict__ ei) {
    int t = blockIdx.x * 256 + threadIdx.x;
    int e = t >> 5;
    int lane = t & 31;
    if (e < N_EDGES) {
        int s = ei[e];
        int d = ei[N_EDGES + e];
        const float4 v = *(const float4*)&g_hs[s * LATENT + lane * 4];
        atomicAdd((float4*)&g_agg[d * LATENT + lane * 4], v);
    }
}

// ---- z = relu(dinv*agg + bg); Z[b] = z z^T -> hi/lo bf16 --------------------
__global__ void k_outer(const float* __restrict__ bg) {
    __shared__ float zs[NN][129];
    int b = blockIdx.x;
    int tid = threadIdx.x;
    for (int idx = tid; idx < NN * LATENT; idx += 256) {
        int n = idx >> 7, c = idx & 127;
        int node = b * NN + n;
        float v = g_dinv[node] * g_agg[node * LATENT + c] + bg[c];
        zs[n][c] = (v > 0.0f) ? v : 0.0f;
    }
    __syncthreads();
    int tn = tid >> 4, tm = tid & 15;
    int n0 = tn * 5, m0 = tm * 5;
    float acc[5][5];
#pragma unroll
    for (int i = 0; i < 5; i++)
#pragma unroll
        for (int j = 0; j < 5; j++) acc[i][j] = 0.0f;
#pragma unroll 4
    for (int c = 0; c < LATENT; c++) {
        float zn[5], zm[5];
#pragma unroll
        for (int i = 0; i < 5; i++) { zn[i] = zs[n0 + i][c]; zm[i] = zs[m0 + i][c]; }
#pragma unroll
        for (int i = 0; i < 5; i++)
#pragma unroll
            for (int j = 0; j < 5; j++) acc[i][j] += zn[i] * zm[j];
    }
    __nv_bfloat16* oh = &g_Zh[b * N2];
    __nv_bfloat16* ol = &g_Zl[b * N2];
#pragma unroll
    for (int i = 0; i < 5; i++)
#pragma unroll
        for (int j = 0; j < 5; j++) {
            __nv_bfloat16 h, l;
            cvt_hilo(acc[i][j], h, l);
            int o = (n0 + i) * NN + (m0 + j);
            oh[o] = h; ol[o] = l;
        }
}

// ---------------- mma.sync bf16 3-pass GEMM ----------------------------------
// 256 threads, D[64 x 64] tile, A hi/lo double-buffered, W streamed via regs.
// which==0: A=Zh/Zl -> g_P1 ; which==1: A=H1h/H1l -> g_P2
__global__ void __launch_bounds__(GT, 3)
k_mma(int which, const float* __restrict__ W, int Ktot, int Nout) {
    extern __shared__ char smem[];
    const uint32_t sb = smem_u32(smem);
    const int tid = threadIdx.x;
    const int lane = tid & 31;
    const int wid = tid >> 5;

    const __nv_bfloat16* __restrict__ Ah = (which == 0) ? g_Zh : g_H1h;
    const __nv_bfloat16* __restrict__ Al = (which == 0) ? g_Zl : g_H1l;
    float* __restrict__ Pbase = (which == 0) ? g_P1 : g_P2;

    const int col0 = blockIdx.x * NT;
    const int Kper = Ktot / gridDim.y;
    const int kbase = blockIdx.y * Kper;
    const int nch = Kper / KC;

    const int n4 = tid & 15;
    const int kr0 = tid >> 4;          // 0..15, +i*16
    float4 wr[4];
    {
        const float* src = W + (size_t)kbase * Nout + col0 + n4 * 4;
#pragma unroll
        for (int i = 0; i < 4; i++)
            wr[i] = *(const float4*)(src + (size_t)(kr0 + i * 16) * Nout);
    }

    const int mstrip = (wid & 3) * 16;
    const int nquad  = (wid >> 2) * 32;
    const int lrow = ((lane >> 3) & 1) * 8 + (lane & 7);
    const int lsel = (lane >> 4) * 8;
    const uint32_t aOff = (uint32_t)(mstrip + lrow) * A_STR_B + lsel * 2;
    const uint32_t wH = sb + SM_WH + (uint32_t)lrow * W_STR_B + (uint32_t)(nquad + lsel) * 2;
    const uint32_t wL = sb + SM_WL + (uint32_t)lrow * W_STR_B + (uint32_t)(nquad + lsel) * 2;

    auto stage_a = [&](int c, int buf) {
        const int kb = kbase + c * KC;
        const uint32_t base = sb + SM_A + (uint32_t)buf * (2 * A_BUF_B);
#pragma unroll
        for (int o = 0; o < 4; o++) {
            int idx = tid + o * GT;
            int sel = idx >> 9;
            int rem = idx & 511;
            int r = rem >> 3, g = rem & 7;
            const __nv_bfloat16* s = (sel ? Al : Ah) + (size_t)r * Ktot + kb + g * 8;
            cp_async16(base + sel * A_BUF_B + r * A_STR_B + g * 16, s);
        }
        cp_commit();
    };

    float acc[4][4];
#pragma unroll
    for (int i = 0; i < 4; i++)
#pragma unroll
        for (int j = 0; j < 4; j++) acc[i][j] = 0.0f;

    stage_a(0, 0);

    for (int c = 0; c < nch; c++) {
        if (c + 1 < nch) stage_a(c + 1, (c + 1) & 1);

        // convert W(c) regs -> hi/lo bf16 k-major smem
#pragma unroll
        for (int i = 0; i < 4; i++) {
            float4 v = wr[i];
            int krow = kr0 + i * 16;
            uint32_t h01 = pack_rn(v.x, v.y);
            uint32_t h23 = pack_rn(v.z, v.w);
            float l0 = v.x - __uint_as_float(h01 << 16);
            float l1 = v.y - __uint_as_float(h01 & 0xffff0000u);
            float l2 = v.z - __uint_as_float(h23 << 16);
            float l3 = v.w - __uint_as_float(h23 & 0xffff0000u);
            uint32_t l01 = pack_rn(l0, l1);
            uint32_t l23 = pack_rn(l2, l3);
            char* ph = smem + SM_WH + krow * W_STR_B + n4 * 8;
            char* pl = smem + SM_WL + krow * W_STR_B + n4 * 8;
            *(uint32_t*)(ph) = h01;  *(uint32_t*)(ph + 4) = h23;
            *(uint32_t*)(pl) = l01;  *(uint32_t*)(pl + 4) = l23;
        }

        if (c + 1 < nch) cp_wait<1>();
        else             cp_wait<0>();
        __syncthreads();

        if (c + 1 < nch) {
            const float* src = W + (size_t)(kbase + (c + 1) * KC) * Nout + col0 + n4 * 4;
#pragma unroll
            for (int i = 0; i < 4; i++)
                wr[i] = *(const float4*)(src + (size_t)(kr0 + i * 16) * Nout);
        }

        const uint32_t aB = sb + SM_A + (uint32_t)(c & 1) * (2 * A_BUF_B);
#pragma unroll
        for (int ks = 0; ks < 4; ks++) {
            uint32_t ah[4], al[4];
            ldsm_x4(ah, aB + aOff + ks * 32);
            ldsm_x4(al, aB + A_BUF_B + aOff + ks * 32);
#pragma unroll
            for (int p = 0; p < 2; p++) {
                uint32_t bh[4], bl[4];
                uint32_t off = (uint32_t)(ks * 16) * W_STR_B + p * 32;
                ldsm_x4t(bh, wH + off);
                ldsm_x4t(bl, wL + off);
#pragma unroll
                for (int q = 0; q < 2; q++) {
                    int nf = p * 2 + q;
                    mma_bf16(acc[nf], ah, bh + q * 2);
                    mma_bf16(acc[nf], ah, bl + q * 2);
                    mma_bf16(acc[nf], al, bh + q * 2);
                }
            }
        }
        __syncthreads();
    }

    // epilogue: raw fp32 partials
    const int g = lane >> 2, t4 = lane & 3;
    float* P = Pbase + (size_t)blockIdx.y * N_GRAPHS * Nout;
#pragma unroll
    for (int nf = 0; nf < 4; nf++) {
        int n = col0 + nquad + nf * 8 + t4 * 2;
#pragma unroll
        for (int h = 0; h < 2; h++) {
            int m = mstrip + g + h * 8;
            *(float2*)&P[(size_t)m * Nout + n] =
                make_float2(acc[nf][h * 2 + 0], acc[nf][h * 2 + 1]);
        }
    }
}

// ---- combine GEMM1 partials -> bias+relu -> H1 hi/lo (float4 vectorized) ----
__global__ void k_combine1(const float* __restrict__ b1) {
    int i4 = (blockIdx.x * 256 + threadIdx.x) * 4;   // 819200/4 = 204800 threads
    const int TOT = N_GRAPHS * HID;
    float4 v = *(const float4*)&g_P1[i4];
#pragma unroll
    for (int s = 1; s < S1; s++) {
        float4 p = *(const float4*)&g_P1[i4 + s * TOT];
        v.x += p.x; v.y += p.y; v.z += p.z; v.w += p.w;
    }
    int col = i4 - (i4 / HID) * HID;
    float4 b = *(const float4*)&b1[col];
    v.x = fmaxf(v.x + b.x, 0.0f);
    v.y = fmaxf(v.y + b.y, 0.0f);
    v.z = fmaxf(v.z + b.z, 0.0f);
    v.w = fmaxf(v.w + b.w, 0.0f);
    uint32_t h01 = pack_rn(v.x, v.y);
    uint32_t h23 = pack_rn(v.z, v.w);
    float l0 = v.x - __uint_as_float(h01 << 16);
    float l1 = v.y - __uint_as_float(h01 & 0xffff0000u);
    float l2 = v.z - __uint_as_float(h23 << 16);
    float l3 = v.w - __uint_as_float(h23 & 0xffff0000u);
    uint2 hh = make_uint2(h01, h23);
    uint2 ll = make_uint2(pack_rn(l0, l1), pack_rn(l2, l3));
    *(uint2*)&g_H1h[i4] = hh;
    *(uint2*)&g_H1l[i4] = ll;
}

// ---- combine GEMM2 partials -> sigmoid -> out (float4 vectorized) -----------
__global__ void k_combine2(const float* __restrict__ b2, float* __restrict__ out) {
    int i4 = (blockIdx.x * 256 + threadIdx.x) * 4;   // 409600/4 = 102400 threads
    const int TOT = N_GRAPHS * N2;
    float4 v = *(const float4*)&g_P2[i4];
#pragma unroll
    for (int s = 1; s < S2; s++) {
        float4 p = *(const float4*)&g_P2[i4 + s * TOT];
        v.x += p.x; v.y += p.y; v.z += p.z; v.w += p.w;
    }
    int col = i4 - (i4 / N2) * N2;
    float4 b = *(const float4*)&b2[col];
    float4 r;
    r.x = 1.0f / (1.0f + expf(-(v.x + b.x)));
    r.y = 1.0f / (1.0f + expf(-(v.y + b.y)));
    r.z = 1.0f / (1.0f + expf(-(v.z + b.z)));
    r.w = 1.0f / (1.0f + expf(-(v.w + b.w)));
    *(float4*)&out[i4] = r;
}

// ---------------- launch ------------------------------------------------------
extern "C" void kernel_launch(void* const* d_in, const int* in_sizes, int n_in,
                              void* d_out, int out_size) {
    const float* x  = (const float*)d_in[0];
    const int*   ei = (const int*)d_in[1];
    const float* Wg = (const float*)d_in[2];
    const float* bg = (const float*)d_in[3];
    const float* W1 = (const float*)d_in[4];
    const float* b1 = (const float*)d_in[5];
    const float* W2 = (const float*)d_in[6];
    const float* b2 = (const float*)d_in[7];
    float* out = (float*)d_out;

    cudaFuncSetAttribute(k_mma, cudaFuncAttributeMaxDynamicSharedMemorySize, SM_TOT);

    k_zero<<<2580, 256>>>();
    k_deg<<<(N_EDGES + 255) / 256, 256>>>(ei);
    k_gemm_h<<<N_NODES / 16, 256>>>(x, Wg);
    k_scatter<<<(N_EDGES * 32) / 256, 256>>>(ei);
    k_outer<<<N_GRAPHS, 256>>>(bg);
    // GEMM1: 200 col tiles x S1=4 = 800 blocks, Kper=1600
    k_mma<<<dim3(HID / NT, S1), GT, SM_TOT>>>(0, W1, N2, HID);
    k_combine1<<<(N_GRAPHS * HID) / 1024, 256>>>(b1);
    // GEMM2: 100 col tiles x S2=8 = 800 blocks, Kper=1600
    k_mma<<<dim3(N2 / NT, S2), GT, SM_TOT>>>(1, W2, HID, N2);
    k_combine2<<<(N_GRAPHS * N2) / 1024, 256>>>(b2, out);
}

// round 12
// speedup vs baseline: 17.1592x; 1.1066x over previous
#include <cuda_runtime.h>
#include <cuda_bf16.h>
#include <math.h>
#include <stdint.h>

#define N_NODES 5120
#define TBL 256
#define LATENT 128
#define N_GRAPHS 64
#define N_EDGES 163840
#define NN 80
#define N2 6400
#define HID 12800

#define KU 3264          // padded upper-triangle K for GEMM1 (3240 real + 24 pad)
#define KUR 3240

#define NT 64            // n cols per GEMM block tile
#define KC 64            // k per chunk
#define GT 256           // threads per GEMM block
#define S1 3             // split-K GEMM1 (600 blocks, Kper=1088)
#define S2 8             // split-K GEMM2 (800 blocks)

// smem layout (bytes)
#define A_STR_B 144
#define W_STR_B 144
#define A_BUF_B 9216                 // 64 rows * 144B, one of hi/lo
#define SM_A 0                       // A: 2 bufs x (hi + lo) = 36864
#define SM_WH 36864
#define SM_WL 46080
#define SM_TOT 55296

typedef unsigned long long ull;

// ---------------- scratch -----------------------------------------------------
__device__ float g_deg[N_NODES];
__device__ float g_dinv[N_NODES];
__device__ float g_hs[N_NODES * LATENT];
__device__ float g_agg[N_NODES * LATENT];
__device__ __align__(256) __nv_bfloat16 g_Zh[N_GRAPHS * KU];   // upper-tri Z hi
__device__ __align__(256) __nv_bfloat16 g_Zl[N_GRAPHS * KU];   // upper-tri Z lo
__device__ __align__(256) __nv_bfloat16 g_H1h[N_GRAPHS * HID];
__device__ __align__(256) __nv_bfloat16 g_H1l[N_GRAPHS * HID];
__device__ float g_P1[S1 * N_GRAPHS * HID];
__device__ float g_P2[S2 * N_GRAPHS * N2];
__device__ int g_t1[KU];             // W1 row for upper index t
__device__ int g_t2[KU];             // partner row (or -1)

// ---------------- helpers -----------------------------------------------------
__device__ __forceinline__ uint32_t smem_u32(const void* p) {
    uint32_t a;
    asm("{ .reg .u64 t; cvta.to.shared.u64 t, %1; cvt.u32.u64 %0, t; }" : "=r"(a) : "l"(p));
    return a;
}
__device__ __forceinline__ void cp_async16(uint32_t dst, const void* src) {
    asm volatile("cp.async.cg.shared.global [%0], [%1], 16;\n" :: "r"(dst), "l"(src));
}
__device__ __forceinline__ void cp_commit() { asm volatile("cp.async.commit_group;\n" ::: "memory"); }
template<int N> __device__ __forceinline__ void cp_wait() {
    asm volatile("cp.async.wait_group %0;\n" :: "n"(N) : "memory");
}
__device__ __forceinline__ void ldsm_x4(uint32_t* r, uint32_t addr) {
    asm volatile("ldmatrix.sync.aligned.m8n8.x4.shared.b16 {%0,%1,%2,%3}, [%4];"
        : "=r"(r[0]), "=r"(r[1]), "=r"(r[2]), "=r"(r[3]) : "r"(addr));
}
__device__ __forceinline__ void ldsm_x4t(uint32_t* r, uint32_t addr) {
    asm volatile("ldmatrix.sync.aligned.m8n8.x4.trans.shared.b16 {%0,%1,%2,%3}, [%4];"
        : "=r"(r[0]), "=r"(r[1]), "=r"(r[2]), "=r"(r[3]) : "r"(addr));
}
__device__ __forceinline__ void mma_bf16(float* c, const uint32_t* a, const uint32_t* b) {
    asm volatile(
        "mma.sync.aligned.m16n8k16.row.col.f32.bf16.bf16.f32 "
        "{%0,%1,%2,%3}, {%4,%5,%6,%7}, {%8,%9}, {%0,%1,%2,%3};\n"
        : "+f"(c[0]), "+f"(c[1]), "+f"(c[2]), "+f"(c[3])
        : "r"(a[0]), "r"(a[1]), "r"(a[2]), "r"(a[3]), "r"(b[0]), "r"(b[1]));
}
__device__ __forceinline__ uint32_t pack_rn(float x, float y) {
    __nv_bfloat162 t = __float22bfloat162_rn(make_float2(x, y));
    return *(uint32_t*)&t;
}
__device__ __forceinline__ void cvt_hilo(float x, __nv_bfloat16& h, __nv_bfloat16& l) {
    h = __float2bfloat16(x);
    l = __float2bfloat16(x - __bfloat162float(h));
}

// ---------------- small kernels ----------------------------------------------
__global__ void k_zero() {
    int t = blockIdx.x * blockDim.x + threadIdx.x;
    if (t < N_NODES) g_deg[t] = 0.0f;
    else g_agg[t - N_NODES] = 0.0f;
}
__global__ void k_deg(const int* __restrict__ ei) {
    int e = blockIdx.x * 256 + threadIdx.x;
    if (e < N_EDGES) atomicAdd(&g_deg[ei[N_EDGES + e]], 1.0f);
}
// row-pair table for upper-tri index t -> W1 rows (n*80+m, m*80+n)
__global__ void k_tab() {
    int t = blockIdx.x * 256 + threadIdx.x;
    if (t >= KU) return;
    if (t >= KUR) { g_t1[t] = 0; g_t2[t] = -1; return; }
    int n = 0, start = 0;
    while (start + (NN - n) <= t) { start += NN - n; n++; }
    int m = n + (t - start);
    g_t1[t] = n * NN + m;
    g_t2[t] = (m > n) ? (m * NN + n) : -1;
}

// ---- hs = (x @ Wg) * dinv[row]; also emits g_dinv ---------------------------
__global__ void k_gemm_h(const float* __restrict__ x, const float* __restrict__ Wg) {
    __shared__ float xs[16][TBL];
    __shared__ float ws[2][16][LATENT];
    int tid = threadIdx.x;
    int col = tid & 127;
    int rh = tid >> 7;
    int rowblk = blockIdx.x * 16;

    uint32_t xs_u = smem_u32(&xs[0][0]);
    uint32_t ws_u = smem_u32(&ws[0][0][0]);

#pragma unroll
    for (int i = 0; i < 4; i++) {
        int idx4 = tid + i * 256;
        int r = idx4 >> 6, k4 = idx4 & 63;
        cp_async16(xs_u + (r * TBL + k4 * 4) * 4,
                   x + (size_t)(rowblk + r) * TBL + k4 * 4);
    }
    auto stage_w = [&](int c) {
#pragma unroll
        for (int i = 0; i < 2; i++) {
            int idx4 = tid + i * 256;
            int k = idx4 >> 5, c4 = idx4 & 31;
            cp_async16(ws_u + ((c & 1) * 16 * LATENT + k * LATENT + c4 * 4) * 4,
                       Wg + (size_t)(c * 16 + k) * LATENT + c4 * 4);
        }
        cp_commit();
    };
    stage_w(0);

    float acc[8];
#pragma unroll
    for (int r = 0; r < 8; r++) acc[r] = 0.0f;

#pragma unroll
    for (int c = 0; c < 16; c++) {
        if (c + 1 < 16) { stage_w(c + 1); cp_wait<1>(); }
        else            { cp_wait<0>(); }
        __syncthreads();
#pragma unroll
        for (int k4 = 0; k4 < 4; k4++) {
            float w0 = ws[c & 1][k4 * 4 + 0][col];
            float w1 = ws[c & 1][k4 * 4 + 1][col];
            float w2 = ws[c & 1][k4 * 4 + 2][col];
            float w3 = ws[c & 1][k4 * 4 + 3][col];
#pragma unroll
            for (int r = 0; r < 8; r++) {
                float4 xv = *(const float4*)&xs[rh * 8 + r][c * 16 + k4 * 4];
                acc[r] += xv.x * w0 + xv.y * w1 + xv.z * w2 + xv.w * w3;
            }
        }
        __syncthreads();
    }

#pragma unroll
    for (int r = 0; r < 8; r++) {
        int node = rowblk + rh * 8 + r;
        float d = g_deg[node];
        float di = (d > 0.0f) ? rsqrtf(d) : 0.0f;
        g_hs[node * LATENT + col] = acc[r] * di;
        if (col == 0) g_dinv[node] = di;
    }
}

__global__ void k_scatter(const int* __restrict__ ei) {
    int t = blockIdx.x * 256 + threadIdx.x;
    int e = t >> 5;
    int lane = t & 31;
    if (e < N_EDGES) {
        int s = ei[e];
        int d = ei[N_EDGES + e];
        const float4 v = *(const float4*)&g_hs[s * LATENT + lane * 4];
        atomicAdd((float4*)&g_agg[d * LATENT + lane * 4], v);
    }
}

// ---- z = relu(dinv*agg + bg); upper-tri of z z^T -> hi/lo bf16 --------------
__global__ void k_outer(const float* __restrict__ bg) {
    __shared__ float zs[NN][129];
    int b = blockIdx.x;
    int tid = threadIdx.x;
    for (int idx = tid; idx < NN * LATENT; idx += 256) {
        int n = idx >> 7, c = idx & 127;
        int node = b * NN + n;
        float v = g_dinv[node] * g_agg[node * LATENT + c] + bg[c];
        zs[n][c] = (v > 0.0f) ? v : 0.0f;
    }
    __syncthreads();
    int tn = tid >> 4, tm = tid & 15;
    int n0 = tn * 5, m0 = tm * 5;
    float acc[5][5];
#pragma unroll
    for (int i = 0; i < 5; i++)
#pragma unroll
        for (int j = 0; j < 5; j++) acc[i][j] = 0.0f;
#pragma unroll 4
    for (int c = 0; c < LATENT; c++) {
        float zn[5], zm[5];
#pragma unroll
        for (int i = 0; i < 5; i++) { zn[i] = zs[n0 + i][c]; zm[i] = zs[m0 + i][c]; }
#pragma unroll
        for (int i = 0; i < 5; i++)
#pragma unroll
            for (int j = 0; j < 5; j++) acc[i][j] += zn[i] * zm[j];
    }
    __nv_bfloat16* oh = &g_Zh[b * KU];
    __nv_bfloat16* ol = &g_Zl[b * KU];
#pragma unroll
    for (int i = 0; i < 5; i++) {
        int n = n0 + i;
        int rowbase = n * NN - (n * (n + 1)) / 2;   // S(n) - n
#pragma unroll
        for (int j = 0; j < 5; j++) {
            int m = m0 + j;
            if (n <= m) {
                __nv_bfloat16 h, l;
                cvt_hilo(acc[i][j], h, l);
                int t = rowbase + m;
                oh[t] = h; ol[t] = l;
            }
        }
    }
    // zero the 24 pad entries
    if (tid < KU - KUR) {
        oh[KUR + tid] = __float2bfloat16(0.0f);
        ol[KUR + tid] = __float2bfloat16(0.0f);
    }
}

// ---------------- GEMM1: upper-tri A, folded-W bf16 3-pass -------------------
// A = Zh/Zl [64][KU]; W1 rows gathered via g_t1/g_t2 and summed in fp32.
__global__ void __launch_bounds__(GT, 2)
k_mma1(const float* __restrict__ W) {
    extern __shared__ char smem[];
    const uint32_t sb = smem_u32(smem);
    const int tid = threadIdx.x;
    const int lane = tid & 31;
    const int wid = tid >> 5;

    const int col0 = blockIdx.x * NT;
    const int Kper = KU / S1;              // 1088
    const int kbase = blockIdx.y * Kper;
    const int nch = Kper / KC;             // 17

    const int n4 = tid & 15;
    const int kr0 = tid >> 4;

    auto ldW = [&](int c, float4* w) {
#pragma unroll
        for (int i = 0; i < 4; i++) {
            int t = kbase + c * KC + kr0 + i * 16;
            int r1 = g_t1[t], r2 = g_t2[t];
            float4 a = *(const float4*)(W + (size_t)r1 * HID + col0 + n4 * 4);
            if (r2 >= 0) {
                float4 bb = *(const float4*)(W + (size_t)r2 * HID + col0 + n4 * 4);
                a.x += bb.x; a.y += bb.y; a.z += bb.z; a.w += bb.w;
            }
            w[i] = a;
        }
    };

    float4 wr[4];
    ldW(0, wr);

    const int mstrip = (wid & 3) * 16;
    const int nquad  = (wid >> 2) * 32;
    const int lrow = ((lane >> 3) & 1) * 8 + (lane & 7);
    const int lsel = (lane >> 4) * 8;
    const uint32_t aOff = (uint32_t)(mstrip + lrow) * A_STR_B + lsel * 2;
    const uint32_t wH = sb + SM_WH + (uint32_t)lrow * W_STR_B + (uint32_t)(nquad + lsel) * 2;
    const uint32_t wL = sb + SM_WL + (uint32_t)lrow * W_STR_B + (uint32_t)(nquad + lsel) * 2;

    auto stage_a = [&](int c, int buf) {
        const int kb = kbase + c * KC;
        const uint32_t base = sb + SM_A + (uint32_t)buf * (2 * A_BUF_B);
#pragma unroll
        for (int o = 0; o < 4; o++) {
            int idx = tid + o * GT;
            int sel = idx >> 9;
            int rem = idx & 511;
            int r = rem >> 3, g = rem & 7;
            const __nv_bfloat16* s = (sel ? g_Zl : g_Zh) + (size_t)r * KU + kb + g * 8;
            cp_async16(base + sel * A_BUF_B + r * A_STR_B + g * 16, s);
        }
        cp_commit();
    };

    float acc[4][4];
#pragma unroll
    for (int i = 0; i < 4; i++)
#pragma unroll
        for (int j = 0; j < 4; j++) acc[i][j] = 0.0f;

    stage_a(0, 0);

    for (int c = 0; c < nch; c++) {
        if (c + 1 < nch) stage_a(c + 1, (c + 1) & 1);

#pragma unroll
        for (int i = 0; i < 4; i++) {
            float4 v = wr[i];
            int krow = kr0 + i * 16;
            uint32_t h01 = pack_rn(v.x, v.y);
            uint32_t h23 = pack_rn(v.z, v.w);
            float l0 = v.x - __uint_as_float(h01 << 16);
            float l1 = v.y - __uint_as_float(h01 & 0xffff0000u);
            float l2 = v.z - __uint_as_float(h23 << 16);
            float l3 = v.w - __uint_as_float(h23 & 0xffff0000u);
            char* ph = smem + SM_WH + krow * W_STR_B + n4 * 8;
            char* pl = smem + SM_WL + krow * W_STR_B + n4 * 8;
            *(uint32_t*)(ph) = h01;  *(uint32_t*)(ph + 4) = h23;
            *(uint32_t*)(pl) = pack_rn(l0, l1);
            *(uint32_t*)(pl + 4) = pack_rn(l2, l3);
        }

        if (c + 1 < nch) cp_wait<1>();
        else             cp_wait<0>();
        __syncthreads();

        if (c + 1 < nch) ldW(c + 1, wr);

        const uint32_t aB = sb + SM_A + (uint32_t)(c & 1) * (2 * A_BUF_B);
#pragma unroll
        for (int ks = 0; ks < 4; ks++) {
            uint32_t ah[4], al[4];
            ldsm_x4(ah, aB + aOff + ks * 32);
            ldsm_x4(al, aB + A_BUF_B + aOff + ks * 32);
#pragma unroll
            for (int p = 0; p < 2; p++) {
                uint32_t bh[4], bl[4];
                uint32_t off = (uint32_t)(ks * 16) * W_STR_B + p * 32;
                ldsm_x4t(bh, wH + off);
                ldsm_x4t(bl, wL + off);
#pragma unroll
                for (int q = 0; q < 2; q++) {
                    int nf = p * 2 + q;
                    mma_bf16(acc[nf], ah, bh + q * 2);
                    mma_bf16(acc[nf], ah, bl + q * 2);
                    mma_bf16(acc[nf], al, bh + q * 2);
                }
            }
        }
        __syncthreads();
    }

    const int g = lane >> 2, t4 = lane & 3;
    float* P = g_P1 + (size_t)blockIdx.y * N_GRAPHS * HID;
#pragma unroll
    for (int nf = 0; nf < 4; nf++) {
        int n = col0 + nquad + nf * 8 + t4 * 2;
#pragma unroll
        for (int h = 0; h < 2; h++) {
            int m = mstrip + g + h * 8;
            *(float2*)&P[(size_t)m * HID + n] =
                make_float2(acc[nf][h * 2 + 0], acc[nf][h * 2 + 1]);
        }
    }
}

// ---------------- GEMM2: H1 bf16 3-pass (unchanged structure) ----------------
__global__ void __launch_bounds__(GT, 3)
k_mma2(const float* __restrict__ W) {
    extern __shared__ char smem[];
    const uint32_t sb = smem_u32(smem);
    const int tid = threadIdx.x;
    const int lane = tid & 31;
    const int wid = tid >> 5;

    const int col0 = blockIdx.x * NT;
    const int Kper = HID / S2;             // 1600
    const int kbase = blockIdx.y * Kper;
    const int nch = Kper / KC;             // 25

    const int n4 = tid & 15;
    const int kr0 = tid >> 4;
    float4 wr[4];
    {
        const float* src = W + (size_t)kbase * N2 + col0 + n4 * 4;
#pragma unroll
        for (int i = 0; i < 4; i++)
            wr[i] = *(const float4*)(src + (size_t)(kr0 + i * 16) * N2);
    }

    const int mstrip = (wid & 3) * 16;
    const int nquad  = (wid >> 2) * 32;
    const int lrow = ((lane >> 3) & 1) * 8 + (lane & 7);
    const int lsel = (lane >> 4) * 8;
    const uint32_t aOff = (uint32_t)(mstrip + lrow) * A_STR_B + lsel * 2;
    const uint32_t wH = sb + SM_WH + (uint32_t)lrow * W_STR_B + (uint32_t)(nquad + lsel) * 2;
    const uint32_t wL = sb + SM_WL + (uint32_t)lrow * W_STR_B + (uint32_t)(nquad + lsel) * 2;

    auto stage_a = [&](int c, int buf) {
        const int kb = kbase + c * KC;
        const uint32_t base = sb + SM_A + (uint32_t)buf * (2 * A_BUF_B);
#pragma unroll
        for (int o = 0; o < 4; o++) {
            int idx = tid + o * GT;
            int sel = idx >> 9;
            int rem = idx & 511;
            int r = rem >> 3, g = rem & 7;
            const __nv_bfloat16* s = (sel ? g_H1l : g_H1h) + (size_t)r * HID + kb + g * 8;
            cp_async16(base + sel * A_BUF_B + r * A_STR_B + g * 16, s);
        }
        cp_commit();
    };

    float acc[4][4];
#pragma unroll
    for (int i = 0; i < 4; i++)
#pragma unroll
        for (int j = 0; j < 4; j++) acc[i][j] = 0.0f;

    stage_a(0, 0);

    for (int c = 0; c < nch; c++) {
        if (c + 1 < nch) stage_a(c + 1, (c + 1) & 1);

#pragma unroll
        for (int i = 0; i < 4; i++) {
            float4 v = wr[i];
            int krow = kr0 + i * 16;
            uint32_t h01 = pack_rn(v.x, v.y);
            uint32_t h23 = pack_rn(v.z, v.w);
            float l0 = v.x - __uint_as_float(h01 << 16);
            float l1 = v.y - __uint_as_float(h01 & 0xffff0000u);
            float l2 = v.z - __uint_as_float(h23 << 16);
            float l3 = v.w - __uint_as_float(h23 & 0xffff0000u);
            char* ph = smem + SM_WH + krow * W_STR_B + n4 * 8;
            char* pl = smem + SM_WL + krow * W_STR_B + n4 * 8;
            *(uint32_t*)(ph) = h01;  *(uint32_t*)(ph + 4) = h23;
            *(uint32_t*)(pl) = pack_rn(l0, l1);
            *(uint32_t*)(pl + 4) = pack_rn(l2, l3);
        }

        if (c + 1 < nch) cp_wait<1>();
        else             cp_wait<0>();
        __syncthreads();

        if (c + 1 < nch) {
            const float* src = W + (size_t)(kbase + (c + 1) * KC) * N2 + col0 + n4 * 4;
#pragma unroll
            for (int i = 0; i < 4; i++)
                wr[i] = *(const float4*)(src + (size_t)(kr0 + i * 16) * N2);
        }

        const uint32_t aB = sb + SM_A + (uint32_t)(c & 1) * (2 * A_BUF_B);
#pragma unroll
        for (int ks = 0; ks < 4; ks++) {
            uint32_t ah[4], al[4];
            ldsm_x4(ah, aB + aOff + ks * 32);
            ldsm_x4(al, aB + A_BUF_B + aOff + ks * 32);
#pragma unroll
            for (int p = 0; p < 2; p++) {
                uint32_t bh[4], bl[4];
                uint32_t off = (uint32_t)(ks * 16) * W_STR_B + p * 32;
                ldsm_x4t(bh, wH + off);
                ldsm_x4t(bl, wL + off);
#pragma unroll
                for (int q = 0; q < 2; q++) {
                    int nf = p * 2 + q;
                    mma_bf16(acc[nf], ah, bh + q * 2);
                    mma_bf16(acc[nf], ah, bl + q * 2);
                    mma_bf16(acc[nf], al, bh + q * 2);
                }
            }
        }
        __syncthreads();
    }

    const int g = lane >> 2, t4 = lane & 3;
    float* P = g_P2 + (size_t)blockIdx.y * N_GRAPHS * N2;
#pragma unroll
    for (int nf = 0; nf < 4; nf++) {
        int n = col0 + nquad + nf * 8 + t4 * 2;
#pragma unroll
        for (int h = 0; h < 2; h++) {
            int m = mstrip + g + h * 8;
            *(float2*)&P[(size_t)m * N2 + n] =
                make_float2(acc[nf][h * 2 + 0], acc[nf][h * 2 + 1]);
        }
    }
}

// ---- combine GEMM1 partials -> bias+relu -> H1 hi/lo ------------------------
__global__ void k_combine1(const float* __restrict__ b1) {
    int i4 = (blockIdx.x * 256 + threadIdx.x) * 4;
    const int TOT = N_GRAPHS * HID;
    float4 v = *(const float4*)&g_P1[i4];
#pragma unroll
    for (int s = 1; s < S1; s++) {
        float4 p = *(const float4*)&g_P1[i4 + s * TOT];
        v.x += p.x; v.y += p.y; v.z += p.z; v.w += p.w;
    }
    int col = i4 - (i4 / HID) * HID;
    float4 b = *(const float4*)&b1[col];
    v.x = fmaxf(v.x + b.x, 0.0f);
    v.y = fmaxf(v.y + b.y, 0.0f);
    v.z = fmaxf(v.z + b.z, 0.0f);
    v.w = fmaxf(v.w + b.w, 0.0f);
    uint32_t h01 = pack_rn(v.x, v.y);
    uint32_t h23 = pack_rn(v.z, v.w);
    float l0 = v.x - __uint_as_float(h01 << 16);
    float l1 = v.y - __uint_as_float(h01 & 0xffff0000u);
    float l2 = v.z - __uint_as_float(h23 << 16);
    float l3 = v.w - __uint_as_float(h23 & 0xffff0000u);
    *(uint2*)&g_H1h[i4] = make_uint2(h01, h23);
    *(uint2*)&g_H1l[i4] = make_uint2(pack_rn(l0, l1), pack_rn(l2, l3));
}

// ---- combine GEMM2 partials -> sigmoid -> out -------------------------------
__global__ void k_combine2(const float* __restrict__ b2, float* __restrict__ out) {
    int i4 = (blockIdx.x * 256 + threadIdx.x) * 4;
    const int TOT = N_GRAPHS * N2;
    float4 v = *(const float4*)&g_P2[i4];
#pragma unroll
    for (int s = 1; s < S2; s++) {
        float4 p = *(const float4*)&g_P2[i4 + s * TOT];
        v.x += p.x; v.y += p.y; v.z += p.z; v.w += p.w;
    }
    int col = i4 - (i4 / N2) * N2;
    float4 b = *(const float4*)&b2[col];
    float4 r;
    r.x = 1.0f / (1.0f + expf(-(v.x + b.x)));
    r.y = 1.0f / (1.0f + expf(-(v.y + b.y)));
    r.z = 1.0f / (1.0f + expf(-(v.z + b.z)));
    r.w = 1.0f / (1.0f + expf(-(v.w + b.w)));
    *(float4*)&out[i4] = r;
}

// ---------------- launch ------------------------------------------------------
extern "C" void kernel_launch(void* const* d_in, const int* in_sizes, int n_in,
                              void* d_out, int out_size) {
    const float* x  = (const float*)d_in[0];
    const int*   ei = (const int*)d_in[1];
    const float* Wg = (const float*)d_in[2];
    const float* bg = (const float*)d_in[3];
    const float* W1 = (const float*)d_in[4];
    const float* b1 = (const float*)d_in[5];
    const float* W2 = (const float*)d_in[6];
    const float* b2 = (const float*)d_in[7];
    float* out = (float*)d_out;

    cudaFuncSetAttribute(k_mma1, cudaFuncAttributeMaxDynamicSharedMemorySize, SM_TOT);
    cudaFuncSetAttribute(k_mma2, cudaFuncAttributeMaxDynamicSharedMemorySize, SM_TOT);

    k_zero<<<2580, 256>>>();
    k_tab<<<(KU + 255) / 256, 256>>>();
    k_deg<<<(N_EDGES + 255) / 256, 256>>>(ei);
    k_gemm_h<<<N_NODES / 16, 256>>>(x, Wg);
    k_scatter<<<(N_EDGES * 32) / 256, 256>>>(ei);
    k_outer<<<N_GRAPHS, 256>>>(bg);
    // GEMM1: 200 col tiles x S1=3 = 600 blocks, K=3264 (upper-tri folded)
    k_mma1<<<dim3(HID / NT, S1), GT, SM_TOT>>>(W1);
    k_combine1<<<(N_GRAPHS * HID) / 1024, 256>>>(b1);
    // GEMM2: 100 col tiles x S2=8 = 800 blocks, Kper=1600
    k_mma2<<<dim3(N2 / NT, S2), GT, SM_TOT>>>(W2);
    k_combine2<<<(N_GRAPHS * N2) / 1024, 256>>>(b2, out);
}

// round 13
// speedup vs baseline: 17.2598x; 1.0059x over previous
#include <cuda_runtime.h>
#include <cuda_bf16.h>
#include <math.h>
#include <stdint.h>

#define N_NODES 5120
#define TBL 256
#define LATENT 128
#define N_GRAPHS 64
#define N_EDGES 163840
#define NN 80
#define N2 6400
#define HID 12800

#define KU 3264          // padded upper-triangle K for GEMM1 (3240 real + 24 pad)
#define KUR 3240

#define NT 64            // n cols per GEMM block tile
#define KC 64            // k per chunk
#define GT 256           // threads per GEMM block
#define S1 3             // split-K GEMM1 (600 blocks, Kper=1088)
#define S2 4             // split-K GEMM2 (400 blocks, Kper=3200)

// smem layout (bytes)
#define A_STR_B 144
#define W_STR_B 144
#define A_BUF_B 9216                 // 64 rows * 144B, one of hi/lo
#define SM_A 0                       // A: 2 bufs x (hi + lo) = 36864
#define SM_WH 36864
#define SM_WL 46080
#define SM_TOT 55296

typedef unsigned long long ull;

// ---------------- scratch -----------------------------------------------------
__device__ float g_deg[N_NODES];
__device__ float g_dinv[N_NODES];
__device__ float g_hs[N_NODES * LATENT];
__device__ float g_agg[N_NODES * LATENT];
__device__ __align__(256) __nv_bfloat16 g_Zh[N_GRAPHS * KU];
__device__ __align__(256) __nv_bfloat16 g_Zl[N_GRAPHS * KU];
__device__ __align__(256) __nv_bfloat16 g_H1h[N_GRAPHS * HID];
__device__ __align__(256) __nv_bfloat16 g_H1l[N_GRAPHS * HID];
__device__ float g_P1[S1 * N_GRAPHS * HID];
__device__ float g_P2[S2 * N_GRAPHS * N2];
__device__ int g_t1[KU];
__device__ int g_t2[KU];

// ---------------- helpers -----------------------------------------------------
__device__ __forceinline__ uint32_t smem_u32(const void* p) {
    uint32_t a;
    asm("{ .reg .u64 t; cvta.to.shared.u64 t, %1; cvt.u32.u64 %0, t; }" : "=r"(a) : "l"(p));
    return a;
}
__device__ __forceinline__ void cp_async16(uint32_t dst, const void* src) {
    asm volatile("cp.async.cg.shared.global [%0], [%1], 16;\n" :: "r"(dst), "l"(src));
}
__device__ __forceinline__ void cp_commit() { asm volatile("cp.async.commit_group;\n" ::: "memory"); }
template<int N> __device__ __forceinline__ void cp_wait() {
    asm volatile("cp.async.wait_group %0;\n" :: "n"(N) : "memory");
}
__device__ __forceinline__ void ldsm_x4(uint32_t* r, uint32_t addr) {
    asm volatile("ldmatrix.sync.aligned.m8n8.x4.shared.b16 {%0,%1,%2,%3}, [%4];"
        : "=r"(r[0]), "=r"(r[1]), "=r"(r[2]), "=r"(r[3]) : "r"(addr));
}
__device__ __forceinline__ void ldsm_x4t(uint32_t* r, uint32_t addr) {
    asm volatile("ldmatrix.sync.aligned.m8n8.x4.trans.shared.b16 {%0,%1,%2,%3}, [%4];"
        : "=r"(r[0]), "=r"(r[1]), "=r"(r[2]), "=r"(r[3]) : "r"(addr));
}
__device__ __forceinline__ void mma_bf16(float* c, const uint32_t* a, const uint32_t* b) {
    asm volatile(
        "mma.sync.aligned.m16n8k16.row.col.f32.bf16.bf16.f32 "
        "{%0,%1,%2,%3}, {%4,%5,%6,%7}, {%8,%9}, {%0,%1,%2,%3};\n"
        : "+f"(c[0]), "+f"(c[1]), "+f"(c[2]), "+f"(c[3])
        : "r"(a[0]), "r"(a[1]), "r"(a[2]), "r"(a[3]), "r"(b[0]), "r"(b[1]));
}
__device__ __forceinline__ uint32_t pack_rn(float x, float y) {
    __nv_bfloat162 t = __float22bfloat162_rn(make_float2(x, y));
    return *(uint32_t*)&t;
}
__device__ __forceinline__ void cvt_hilo(float x, __nv_bfloat16& h, __nv_bfloat16& l) {
    h = __float2bfloat16(x);
    l = __float2bfloat16(x - __bfloat162float(h));
}

// ---------------- K0: zero deg + build fold table ----------------------------
__global__ void k_pre() {
    int t = blockIdx.x * 256 + threadIdx.x;    // grid 20 x 256 = 5120
    if (t < N_NODES) g_deg[t] = 0.0f;
    if (t < KU) {
        if (t >= KUR) { g_t1[t] = 0; g_t2[t] = -1; return; }
        int n = 0, start = 0;
        while (start + (NN - n) <= t) { start += NN - n; n++; }
        int m = n + (t - start);
        g_t1[t] = n * NN + m;
        g_t2[t] = (m > n) ? (m * NN + n) : -1;
    }
}

__global__ void k_deg(const int* __restrict__ ei) {
    int e = blockIdx.x * 256 + threadIdx.x;
    if (e < N_EDGES) atomicAdd(&g_deg[ei[N_EDGES + e]], 1.0f);
}

// ---- hs = (x @ Wg) * dinv[row]; emits g_dinv; also zeroes g_agg slice -------
__global__ void k_gemm_h(const float* __restrict__ x, const float* __restrict__ Wg) {
    __shared__ float xs[16][TBL];
    __shared__ float ws[2][16][LATENT];
    int tid = threadIdx.x;
    int col = tid & 127;
    int rh = tid >> 7;
    int rowblk = blockIdx.x * 16;

    // zero this block's slice of g_agg (655360 floats / 320 blocks = 2048)
    {
        int base = (blockIdx.x * 256 + tid) * 8;
        *(float4*)&g_agg[base] = make_float4(0.f, 0.f, 0.f, 0.f);
        *(float4*)&g_agg[base + 4] = make_float4(0.f, 0.f, 0.f, 0.f);
    }

    uint32_t xs_u = smem_u32(&xs[0][0]);
    uint32_t ws_u = smem_u32(&ws[0][0][0]);

#pragma unroll
    for (int i = 0; i < 4; i++) {
        int idx4 = tid + i * 256;
        int r = idx4 >> 6, k4 = idx4 & 63;
        cp_async16(xs_u + (r * TBL + k4 * 4) * 4,
                   x + (size_t)(rowblk + r) * TBL + k4 * 4);
    }
    auto stage_w = [&](int c) {
#pragma unroll
        for (int i = 0; i < 2; i++) {
            int idx4 = tid + i * 256;
            int k = idx4 >> 5, c4 = idx4 & 31;
            cp_async16(ws_u + ((c & 1) * 16 * LATENT + k * LATENT + c4 * 4) * 4,
                       Wg + (size_t)(c * 16 + k) * LATENT + c4 * 4);
        }
        cp_commit();
    };
    stage_w(0);

    float acc[8];
#pragma unroll
    for (int r = 0; r < 8; r++) acc[r] = 0.0f;

#pragma unroll
    for (int c = 0; c < 16; c++) {
        if (c + 1 < 16) { stage_w(c + 1); cp_wait<1>(); }
        else            { cp_wait<0>(); }
        __syncthreads();
#pragma unroll
        for (int k4 = 0; k4 < 4; k4++) {
            float w0 = ws[c & 1][k4 * 4 + 0][col];
            float w1 = ws[c & 1][k4 * 4 + 1][col];
            float w2 = ws[c & 1][k4 * 4 + 2][col];
            float w3 = ws[c & 1][k4 * 4 + 3][col];
#pragma unroll
            for (int r = 0; r < 8; r++) {
                float4 xv = *(const float4*)&xs[rh * 8 + r][c * 16 + k4 * 4];
                acc[r] += xv.x * w0 + xv.y * w1 + xv.z * w2 + xv.w * w3;
            }
        }
        __syncthreads();
    }

#pragma unroll
    for (int r = 0; r < 8; r++) {
        int node = rowblk + rh * 8 + r;
        float d = g_deg[node];
        float di = (d > 0.0f) ? rsqrtf(d) : 0.0f;
        g_hs[node * LATENT + col] = acc[r] * di;
        if (col == 0) g_dinv[node] = di;
    }
}

__global__ void k_scatter(const int* __restrict__ ei) {
    int t = blockIdx.x * 256 + threadIdx.x;
    int e = t >> 5;
    int lane = t & 31;
    if (e < N_EDGES) {
        int s = ei[e];
        int d = ei[N_EDGES + e];
        const float4 v = *(const float4*)&g_hs[s * LATENT + lane * 4];
        atomicAdd((float4*)&g_agg[d * LATENT + lane * 4], v);
    }
}

// ---- z = relu(dinv*agg + bg); upper-tri of z z^T -> hi/lo bf16 --------------
// 128 blocks (2 per graph). Lane pairs split LATENT; shfl_down reduce.
__global__ void k_outer(const float* __restrict__ bg) {
    __shared__ float zs[NN][129];
    int b = blockIdx.x >> 1;
    int half = blockIdx.x & 1;
    int tid = threadIdx.x;

    for (int idx = tid; idx < NN * LATENT; idx += 256) {
        int n = idx >> 7, c = idx & 127;
        int node = b * NN + n;
        float v = g_dinv[node] * g_agg[node * LATENT + c] + bg[c];
        zs[n][c] = (v > 0.0f) ? v : 0.0f;
    }
    __syncthreads();

    int tile = tid >> 1;              // 0..127
    int ksel = tid & 1;
    int tn = half * 8 + (tile >> 4);  // 0..15
    int tm = tile & 15;
    int n0 = tn * 5, m0 = tm * 5;

    float acc[5][5];
#pragma unroll
    for (int i = 0; i < 5; i++)
#pragma unroll
        for (int j = 0; j < 5; j++) acc[i][j] = 0.0f;

#pragma unroll 4
    for (int c2 = 0; c2 < 64; c2++) {
        int c = 2 * c2 + ksel;
        float zn[5], zm[5];
#pragma unroll
        for (int i = 0; i < 5; i++) { zn[i] = zs[n0 + i][c]; zm[i] = zs[m0 + i][c]; }
#pragma unroll
        for (int i = 0; i < 5; i++)
#pragma unroll
            for (int j = 0; j < 5; j++) acc[i][j] += zn[i] * zm[j];
    }

    // pair reduce: even lane accumulates odd lane's partial
#pragma unroll
    for (int i = 0; i < 5; i++)
#pragma unroll
        for (int j = 0; j < 5; j++)
            acc[i][j] += __shfl_down_sync(0xffffffffu, acc[i][j], 1);

    __nv_bfloat16* oh = &g_Zh[b * KU];
    __nv_bfloat16* ol = &g_Zl[b * KU];
    if (ksel == 0) {
#pragma unroll
        for (int i = 0; i < 5; i++) {
            int n = n0 + i;
            int rowbase = n * NN - (n * (n + 1)) / 2;
#pragma unroll
            for (int j = 0; j < 5; j++) {
                int m = m0 + j;
                if (n <= m) {
                    __nv_bfloat16 h, l;
                    cvt_hilo(acc[i][j], h, l);
                    int t = rowbase + m;
                    oh[t] = h; ol[t] = l;
                }
            }
        }
    }
    if (half == 0 && tid < KU - KUR) {
        oh[KUR + tid] = __float2bfloat16(0.0f);
        ol[KUR + tid] = __float2bfloat16(0.0f);
    }
}

// ---------------- GEMM1: upper-tri A, folded-W bf16 3-pass -------------------
__global__ void __launch_bounds__(GT, 2)
k_mma1(const float* __restrict__ W) {
    extern __shared__ char smem[];
    const uint32_t sb = smem_u32(smem);
    const int tid = threadIdx.x;
    const int lane = tid & 31;
    const int wid = tid >> 5;

    const int col0 = blockIdx.x * NT;
    const int Kper = KU / S1;
    const int kbase = blockIdx.y * Kper;
    const int nch = Kper / KC;

    const int n4 = tid & 15;
    const int kr0 = tid >> 4;

    auto ldW = [&](int c, float4* w) {
#pragma unroll
        for (int i = 0; i < 4; i++) {
            int t = kbase + c * KC + kr0 + i * 16;
            int r1 = g_t1[t], r2 = g_t2[t];
            float4 a = *(const float4*)(W + (size_t)r1 * HID + col0 + n4 * 4);
            if (r2 >= 0) {
                float4 bb = *(const float4*)(W + (size_t)r2 * HID + col0 + n4 * 4);
                a.x += bb.x; a.y += bb.y; a.z += bb.z; a.w += bb.w;
            }
            w[i] = a;
        }
    };

    float4 wr[4];
    ldW(0, wr);

    const int mstrip = (wid & 3) * 16;
    const int nquad  = (wid >> 2) * 32;
    const int lrow = ((lane >> 3) & 1) * 8 + (lane & 7);
    const int lsel = (lane >> 4) * 8;
    const uint32_t aOff = (uint32_t)(mstrip + lrow) * A_STR_B + lsel * 2;
    const uint32_t wH = sb + SM_WH + (uint32_t)lrow * W_STR_B + (uint32_t)(nquad + lsel) * 2;
    const uint32_t wL = sb + SM_WL + (uint32_t)lrow * W_STR_B + (uint32_t)(nquad + lsel) * 2;

    auto stage_a = [&](int c, int buf) {
        const int kb = kbase + c * KC;
        const uint32_t base = sb + SM_A + (uint32_t)buf * (2 * A_BUF_B);
#pragma unroll
        for (int o = 0; o < 4; o++) {
            int idx = tid + o * GT;
            int sel = idx >> 9;
            int rem = idx & 511;
            int r = rem >> 3, g = rem & 7;
            const __nv_bfloat16* s = (sel ? g_Zl : g_Zh) + (size_t)r * KU + kb + g * 8;
            cp_async16(base + sel * A_BUF_B + r * A_STR_B + g * 16, s);
        }
        cp_commit();
    };

    float acc[4][4];
#pragma unroll
    for (int i = 0; i < 4; i++)
#pragma unroll
        for (int j = 0; j < 4; j++) acc[i][j] = 0.0f;

    stage_a(0, 0);

    for (int c = 0; c < nch; c++) {
        if (c + 1 < nch) stage_a(c + 1, (c + 1) & 1);

#pragma unroll
        for (int i = 0; i < 4; i++) {
            float4 v = wr[i];
            int krow = kr0 + i * 16;
            uint32_t h01 = pack_rn(v.x, v.y);
            uint32_t h23 = pack_rn(v.z, v.w);
            float l0 = v.x - __uint_as_float(h01 << 16);
            float l1 = v.y - __uint_as_float(h01 & 0xffff0000u);
            float l2 = v.z - __uint_as_float(h23 << 16);
            float l3 = v.w - __uint_as_float(h23 & 0xffff0000u);
            char* ph = smem + SM_WH + krow * W_STR_B + n4 * 8;
            char* pl = smem + SM_WL + krow * W_STR_B + n4 * 8;
            *(uint32_t*)(ph) = h01;  *(uint32_t*)(ph + 4) = h23;
            *(uint32_t*)(pl) = pack_rn(l0, l1);
            *(uint32_t*)(pl + 4) = pack_rn(l2, l3);
        }

        if (c + 1 < nch) cp_wait<1>();
        else             cp_wait<0>();
        __syncthreads();

        if (c + 1 < nch) ldW(c + 1, wr);

        const uint32_t aB = sb + SM_A + (uint32_t)(c & 1) * (2 * A_BUF_B);
#pragma unroll
        for (int ks = 0; ks < 4; ks++) {
            uint32_t ah[4], al[4];
            ldsm_x4(ah, aB + aOff + ks * 32);
            ldsm_x4(al, aB + A_BUF_B + aOff + ks * 32);
#pragma unroll
            for (int p = 0; p < 2; p++) {
                uint32_t bh[4], bl[4];
                uint32_t off = (uint32_t)(ks * 16) * W_STR_B + p * 32;
                ldsm_x4t(bh, wH + off);
                ldsm_x4t(bl, wL + off);
#pragma unroll
                for (int q = 0; q < 2; q++) {
                    int nf = p * 2 + q;
                    mma_bf16(acc[nf], ah, bh + q * 2);
                    mma_bf16(acc[nf], ah, bl + q * 2);
                    mma_bf16(acc[nf], al, bh + q * 2);
                }
            }
        }
        __syncthreads();
    }

    const int g = lane >> 2, t4 = lane & 3;
    float* P = g_P1 + (size_t)blockIdx.y * N_GRAPHS * HID;
#pragma unroll
    for (int nf = 0; nf < 4; nf++) {
        int n = col0 + nquad + nf * 8 + t4 * 2;
#pragma unroll
        for (int h = 0; h < 2; h++) {
            int m = mstrip + g + h * 8;
            *(float2*)&P[(size_t)m * HID + n] =
                make_float2(acc[nf][h * 2 + 0], acc[nf][h * 2 + 1]);
        }
    }
}

// ---------------- GEMM2: H1 bf16 3-pass --------------------------------------
__global__ void __launch_bounds__(GT, 3)
k_mma2(const float* __restrict__ W) {
    extern __shared__ char smem[];
    const uint32_t sb = smem_u32(smem);
    const int tid = threadIdx.x;
    const int lane = tid & 31;
    const int wid = tid >> 5;

    const int col0 = blockIdx.x * NT;
    const int Kper = HID / S2;             // 3200
    const int kbase = blockIdx.y * Kper;
    const int nch = Kper / KC;             // 50

    const int n4 = tid & 15;
    const int kr0 = tid >> 4;
    float4 wr[4];
    {
        const float* src = W + (size_t)kbase * N2 + col0 + n4 * 4;
#pragma unroll
        for (int i = 0; i < 4; i++)
            wr[i] = *(const float4*)(src + (size_t)(kr0 + i * 16) * N2);
    }

    const int mstrip = (wid & 3) * 16;
    const int nquad  = (wid >> 2) * 32;
    const int lrow = ((lane >> 3) & 1) * 8 + (lane & 7);
    const int lsel = (lane >> 4) * 8;
    const uint32_t aOff = (uint32_t)(mstrip + lrow) * A_STR_B + lsel * 2;
    const uint32_t wH = sb + SM_WH + (uint32_t)lrow * W_STR_B + (uint32_t)(nquad + lsel) * 2;
    const uint32_t wL = sb + SM_WL + (uint32_t)lrow * W_STR_B + (uint32_t)(nquad + lsel) * 2;

    auto stage_a = [&](int c, int buf) {
        const int kb = kbase + c * KC;
        const uint32_t base = sb + SM_A + (uint32_t)buf * (2 * A_BUF_B);
#pragma unroll
        for (int o = 0; o < 4; o++) {
            int idx = tid + o * GT;
            int sel = idx >> 9;
            int rem = idx & 511;
            int r = rem >> 3, g = rem & 7;
            const __nv_bfloat16* s = (sel ? g_H1l : g_H1h) + (size_t)r * HID + kb + g * 8;
            cp_async16(base + sel * A_BUF_B + r * A_STR_B + g * 16, s);
        }
        cp_commit();
    };

    float acc[4][4];
#pragma unroll
    for (int i = 0; i < 4; i++)
#pragma unroll
        for (int j = 0; j < 4; j++) acc[i][j] = 0.0f;

    stage_a(0, 0);

    for (int c = 0; c < nch; c++) {
        if (c + 1 < nch) stage_a(c + 1, (c + 1) & 1);

#pragma unroll
        for (int i = 0; i < 4; i++) {
            float4 v = wr[i];
            int krow = kr0 + i * 16;
            uint32_t h01 = pack_rn(v.x, v.y);
            uint32_t h23 = pack_rn(v.z, v.w);
            float l0 = v.x - __uint_as_float(h01 << 16);
            float l1 = v.y - __uint_as_float(h01 & 0xffff0000u);
            float l2 = v.z - __uint_as_float(h23 << 16);
            float l3 = v.w - __uint_as_float(h23 & 0xffff0000u);
            char* ph = smem + SM_WH + krow * W_STR_B + n4 * 8;
            char* pl = smem + SM_WL + krow * W_STR_B + n4 * 8;
            *(uint32_t*)(ph) = h01;  *(uint32_t*)(ph + 4) = h23;
            *(uint32_t*)(pl) = pack_rn(l0, l1);
            *(uint32_t*)(pl + 4) = pack_rn(l2, l3);
        }

        if (c + 1 < nch) cp_wait<1>();
        else             cp_wait<0>();
        __syncthreads();

        if (c + 1 < nch) {
            const float* src = W + (size_t)(kbase + (c + 1) * KC) * N2 + col0 + n4 * 4;
#pragma unroll
            for (int i = 0; i < 4; i++)
                wr[i] = *(const float4*)(src + (size_t)(kr0 + i * 16) * N2);
        }

        const uint32_t aB = sb + SM_A + (uint32_t)(c & 1) * (2 * A_BUF_B);
#pragma unroll
        for (int ks = 0; ks < 4; ks++) {
            uint32_t ah[4], al[4];
            ldsm_x4(ah, aB + aOff + ks * 32);
            ldsm_x4(al, aB + A_BUF_B + aOff + ks * 32);
#pragma unroll
            for (int p = 0; p < 2; p++) {
                uint32_t bh[4], bl[4];
                uint32_t off = (uint32_t)(ks * 16) * W_STR_B + p * 32;
                ldsm_x4t(bh, wH + off);
                ldsm_x4t(bl, wL + off);
#pragma unroll
                for (int q = 0; q < 2; q++) {
                    int nf = p * 2 + q;
                    mma_bf16(acc[nf], ah, bh + q * 2);
                    mma_bf16(acc[nf], ah, bl + q * 2);
                    mma_bf16(acc[nf], al, bh + q * 2);
                }
            }
        }
        __syncthreads();
    }

    const int g = lane >> 2, t4 = lane & 3;
    float* P = g_P2 + (size_t)blockIdx.y * N_GRAPHS * N2;
#pragma unroll
    for (int nf = 0; nf < 4; nf++) {
        int n = col0 + nquad + nf * 8 + t4 * 2;
#pragma unroll
        for (int h = 0; h < 2; h++) {
            int m = mstrip + g + h * 8;
            *(float2*)&P[(size_t)m * N2 + n] =
                make_float2(acc[nf][h * 2 + 0], acc[nf][h * 2 + 1]);
        }
    }
}

// ---- combine GEMM1 partials -> bias+relu -> H1 hi/lo ------------------------
__global__ void k_combine1(const float* __restrict__ b1) {
    int i4 = (blockIdx.x * 256 + threadIdx.x) * 4;
    const int TOT = N_GRAPHS * HID;
    float4 v = *(const float4*)&g_P1[i4];
#pragma unroll
    for (int s = 1; s < S1; s++) {
        float4 p = *(const float4*)&g_P1[i4 + s * TOT];
        v.x += p.x; v.y += p.y; v.z += p.z; v.w += p.w;
    }
    int col = i4 - (i4 / HID) * HID;
    float4 b = *(const float4*)&b1[col];
    v.x = fmaxf(v.x + b.x, 0.0f);
    v.y = fmaxf(v.y + b.y, 0.0f);
    v.z = fmaxf(v.z + b.z, 0.0f);
    v.w = fmaxf(v.w + b.w, 0.0f);
    uint32_t h01 = pack_rn(v.x, v.y);
    uint32_t h23 = pack_rn(v.z, v.w);
    float l0 = v.x - __uint_as_float(h01 << 16);
    float l1 = v.y - __uint_as_float(h01 & 0xffff0000u);
    float l2 = v.z - __uint_as_float(h23 << 16);
    float l3 = v.w - __uint_as_float(h23 & 0xffff0000u);
    *(uint2*)&g_H1h[i4] = make_uint2(h01, h23);
    *(uint2*)&g_H1l[i4] = make_uint2(pack_rn(l0, l1), pack_rn(l2, l3));
}

// ---- combine GEMM2 partials -> sigmoid -> out -------------------------------
__global__ void k_combine2(const float* __restrict__ b2, float* __restrict__ out) {
    int i4 = (blockIdx.x * 256 + threadIdx.x) * 4;
    const int TOT = N_GRAPHS * N2;
    float4 v = *(const float4*)&g_P2[i4];
#pragma unroll
    for (int s = 1; s < S2; s++) {
        float4 p = *(const float4*)&g_P2[i4 + s * TOT];
        v.x += p.x; v.y += p.y; v.z += p.z; v.w += p.w;
    }
    int col = i4 - (i4 / N2) * N2;
    float4 b = *(const float4*)&b2[col];
    float4 r;
    r.x = 1.0f / (1.0f + expf(-(v.x + b.x)));
    r.y = 1.0f / (1.0f + expf(-(v.y + b.y)));
    r.z = 1.0f / (1.0f + expf(-(v.z + b.z)));
    r.w = 1.0f / (1.0f + expf(-(v.w + b.w)));
    *(float4*)&out[i4] = r;
}

// ---------------- launch ------------------------------------------------------
extern "C" void kernel_launch(void* const* d_in, const int* in_sizes, int n_in,
                              void* d_out, int out_size) {
    const float* x  = (const float*)d_in[0];
    const int*   ei = (const int*)d_in[1];
    const float* Wg = (const float*)d_in[2];
    const float* bg = (const float*)d_in[3];
    const float* W1 = (const float*)d_in[4];
    const float* b1 = (const float*)d_in[5];
    const float* W2 = (const float*)d_in[6];
    const float* b2 = (const float*)d_in[7];
    float* out = (float*)d_out;

    cudaFuncSetAttribute(k_mma1, cudaFuncAttributeMaxDynamicSharedMemorySize, SM_TOT);
    cudaFuncSetAttribute(k_mma2, cudaFuncAttributeMaxDynamicSharedMemorySize, SM_TOT);
    cudaFuncSetAttribute(k_gemm_h, cudaFuncAttributePreferredSharedMemoryCarveout, 100);

    k_pre<<<N_NODES / 256, 256>>>();
    k_deg<<<(N_EDGES + 255) / 256, 256>>>(ei);
    k_gemm_h<<<N_NODES / 16, 256>>>(x, Wg);
    k_scatter<<<(N_EDGES * 32) / 256, 256>>>(ei);
    k_outer<<<2 * N_GRAPHS, 256>>>(bg);
    // GEMM1: 200 col tiles x S1=3 = 600 blocks, K=3264 (upper-tri folded)
    k_mma1<<<dim3(HID / NT, S1), GT, SM_TOT>>>(W1);
    k_combine1<<<(N_GRAPHS * HID) / 1024, 256>>>(b1);
    // GEMM2: 100 col tiles x S2=4 = 400 blocks, Kper=3200
    k_mma2<<<dim3(N2 / NT, S2), GT, SM_TOT>>>(W2);
    k_combine2<<<(N_GRAPHS * N2) / 1024, 256>>>(b2, out);
}